// round 9
// baseline (speedup 1.0000x reference)
#include <cuda_runtime.h>
#include <cuda_bf16.h>
#include <stdint.h>
#include <math.h>

#define NR 6144
#define HD 256
#define G4 1024
#define TT 30
#define QS 16319.0f

// ---------------- static device scratch ----------------
__device__ __nv_bfloat16 g_comb_h[NR*HD], g_comb_l[NR*HD];
__device__ float         g_hidden[NR*HD];
__device__ __nv_bfloat16 g_hid_h[NR*HD], g_hid_l[NR*HD];
__device__ float         g_ep[NR*2];
__device__ float         g_gx0[NR*G4];
__device__ __nv_bfloat16 g_Whid_h[HD*HD], g_Whid_l[HD*HD];
__device__ __nv_bfloat16 g_Wih0_h[G4*HD], g_Wih0_l[G4*HD];
__device__ float g_Wih0ep[G4*2];
__device__ float g_bih0p[G4], g_bhh0p[G4], g_bsum1p[G4];
__device__ float g_c0[NR*HD], g_c1[NR*HD];
__device__ float g_traj[NR*TT*HD];
// int8 path
__device__ __align__(128) int8_t g_h0a[2][NR*HD], g_h0b[2][NR*HD];
__device__ __align__(128) int8_t g_h2a[2][NR*HD], g_h2b[2][NR*HD];
__device__ __align__(128) int8_t g_Whh0qa[G4*HD], g_Whh0qb[G4*HD];
__device__ __align__(128) int8_t g_W1qa[G4*512],  g_W1qb[G4*512];
__device__ float g_cwhh0[G4], g_cw1[G4];

#define OUT_CONF 368640
#define OUT_EP   374784

// ---------------- helpers ----------------
__device__ __forceinline__ void split2(float x, __nv_bfloat16& h, __nv_bfloat16& l){
    h = __float2bfloat16(x);
    l = __float2bfloat16(x - __bfloat162float(h));
}
__device__ __forceinline__ float sigm(float x){ return 1.0f/(1.0f+expf(-x)); }
__device__ __forceinline__ void qpack(float h, int8_t& a, int8_t& b){
    int hq = __float2int_rn(h * QS);
    int ha = (hq + 64) >> 7;
    a = (int8_t)ha; b = (int8_t)(hq - (ha << 7));
}
__device__ __forceinline__ void cp16(void* sdst, const void* gsrc){
    unsigned sa = (unsigned)__cvta_generic_to_shared(sdst);
    asm volatile("cp.async.cg.shared.global [%0], [%1], 16;\n" :: "r"(sa), "l"(gsrc));
}
__device__ __forceinline__ void cp_commit(){ asm volatile("cp.async.commit_group;\n"); }
__device__ __forceinline__ void cp_wait2(){ asm volatile("cp.async.wait_group 2;\n"); }
__device__ __forceinline__ void cp_wait1(){ asm volatile("cp.async.wait_group 1;\n"); }
__device__ __forceinline__ void cp_wait0(){ asm volatile("cp.async.wait_group 0;\n"); }
__device__ __forceinline__ void ldsm4(uint32_t* r, uint32_t a){
    asm volatile("ldmatrix.sync.aligned.m8n8.x4.shared.b16 {%0,%1,%2,%3},[%4];\n"
        : "=r"(r[0]), "=r"(r[1]), "=r"(r[2]), "=r"(r[3]) : "r"(a));
}
__device__ __forceinline__ void mma_bf16(float* c, const uint32_t* a, uint32_t b0, uint32_t b1){
    asm volatile("mma.sync.aligned.m16n8k16.row.col.f32.bf16.bf16.f32 "
        "{%0,%1,%2,%3},{%4,%5,%6,%7},{%8,%9},{%0,%1,%2,%3};\n"
        : "+f"(c[0]), "+f"(c[1]), "+f"(c[2]), "+f"(c[3])
        : "r"(a[0]), "r"(a[1]), "r"(a[2]), "r"(a[3]), "r"(b0), "r"(b1));
}
__device__ __forceinline__ void imma8(int* c, const uint32_t* a, uint32_t b0, uint32_t b1){
    asm volatile("mma.sync.aligned.m16n8k32.row.col.s32.s8.s8.s32 "
        "{%0,%1,%2,%3},{%4,%5,%6,%7},{%8,%9},{%0,%1,%2,%3};\n"
        : "+r"(c[0]), "+r"(c[1]), "+r"(c[2]), "+r"(c[3])
        : "r"(a[0]), "r"(a[1]), "r"(a[2]), "r"(a[3]), "r"(b0), "r"(b1));
}

// ---------------- prep ----------------
__global__ void prep_w(const float* __restrict__ Whid, const float* __restrict__ Wih0,
                       const float* __restrict__ bih0, const float* __restrict__ bhh0,
                       const float* __restrict__ bih1, const float* __restrict__ bhh1){
    const int T0 = 65536, T1 = T0 + 262144, T2 = T1 + 1024;
    for (int i = blockIdx.x*blockDim.x + threadIdx.x; i < T2; i += gridDim.x*blockDim.x){
        if (i < T0){
            split2(Whid[i], g_Whid_h[i], g_Whid_l[i]);
        } else if (i < T1){
            int j = i - T0; int p = j >> 8, k = j & 255;
            int sr = (p & 3)*256 + (p >> 2);
            split2(Wih0[sr*258 + k], g_Wih0_h[j], g_Wih0_l[j]);
        } else {
            int p = i - T1;
            int sr = (p & 3)*256 + (p >> 2);
            g_bih0p[p]  = bih0[sr];
            g_bhh0p[p]  = bhh0[sr];
            g_bsum1p[p] = bih1[sr] + bhh1[sr];
            g_Wih0ep[p*2]   = Wih0[sr*258 + 256];
            g_Wih0ep[p*2+1] = Wih0[sr*258 + 257];
        }
    }
}

__global__ void prep_wq(const float* __restrict__ Whh0, const float* __restrict__ Wih1,
                        const float* __restrict__ Whh1){
    int task = blockIdx.x*8 + (threadIdx.x >> 5);
    int lane = threadIdx.x & 31;
    if (task >= 2048) return;
    bool isW1 = task >= 1024;
    int p  = isW1 ? task - 1024 : task;
    int sr = (p & 3)*256 + (p >> 2);
    int K  = isW1 ? 512 : 256;
    float mx = 0.0f;
    for (int k = lane; k < K; k += 32){
        float w = isW1 ? (k < 256 ? Wih1[sr*256 + k] : Whh1[sr*256 + (k - 256)])
                       : Whh0[sr*256 + k];
        mx = fmaxf(mx, fabsf(w));
    }
    #pragma unroll
    for (int o = 16; o; o >>= 1) mx = fmaxf(mx, __shfl_xor_sync(0xffffffffu, mx, o));
    float scale = QS / fmaxf(mx, 1e-20f);
    for (int k = lane; k < K; k += 32){
        float w = isW1 ? (k < 256 ? Wih1[sr*256 + k] : Whh1[sr*256 + (k - 256)])
                       : Whh0[sr*256 + k];
        int q = __float2int_rn(w * scale);
        int a = (q + 64) >> 7;
        int b = q - (a << 7);
        if (isW1){ g_W1qa[p*512 + k] = (int8_t)a; g_W1qb[p*512 + k] = (int8_t)b; }
        else     { g_Whh0qa[p*256 + k] = (int8_t)a; g_Whh0qb[p*256 + k] = (int8_t)b; }
    }
    if (lane == 0){
        float c = mx / (QS * QS);
        if (isW1) g_cw1[p] = c; else g_cwhh0[p] = c;
    }
}

__global__ void prep_in(const float* __restrict__ obs, const float* __restrict__ lanef,
                        const float* __restrict__ ds){
    for (int idx = blockIdx.x*blockDim.x + threadIdx.x; idx < NR*HD; idx += gridDim.x*blockDim.x){
        int row = idx >> 8, col = idx & 255;
        int b = row / 6, kk = row - b*6;
        float v;
        if (col < 128)      v = obs[b*128 + col];
        else if (col < 192) v = lanef[b*64 + (col - 128)];
        else                v = ds[kk*64 + (col - 192)];
        split2(v, g_comb_h[idx], g_comb_l[idx]);
        g_c1[idx] = 0.0f;
    }
}

// ---------------- bf16 split GEMM: 0=encoder, 1=gx0 (+fused layer0 t=0) ----------------
#define AHI 0
#define ALO 10240
#define BHI 20480
#define BLO 30720
#define STB 40960

__global__ void __launch_bounds__(256, 2)
gemm_k(int mode, const float* __restrict__ bvec)
{
    extern __shared__ __align__(16) char smem[];
    const int tid = threadIdx.x, lane = tid & 31, w = tid >> 5;
    const int wm = w >> 1, wn = w & 1;
    const int bx = blockIdx.x, by = blockIdx.y;

    const __nv_bfloat16 *Ah, *Al, *Bh, *Bl;
    if (mode == 0){ Ah=g_comb_h; Al=g_comb_l; Bh=g_Whid_h; Bl=g_Whid_l; }
    else          { Ah=g_hid_h;  Al=g_hid_l;  Bh=g_Wih0_h; Bl=g_Wih0_l; }

    float acc[2][8][4];
    #pragma unroll
    for (int i = 0; i < 2; i++)
        #pragma unroll
        for (int j = 0; j < 8; j++)
            #pragma unroll
            for (int q = 0; q < 4; q++) acc[i][j][q] = 0.0f;

    const int lrow = tid >> 1, lcg = (tid & 1) * 16;

    auto prefetch = [&](int kb, int st){
        int k0 = kb * 32;
        char* sb = smem + st * STB;
        const __nv_bfloat16* as  = Ah + (bx*128 + lrow)*256 + k0 + lcg;
        const __nv_bfloat16* as2 = Al + (bx*128 + lrow)*256 + k0 + lcg;
        int so = (lrow*40 + lcg)*2;
        cp16(sb + AHI + so, as);   cp16(sb + AHI + so + 16, as + 8);
        cp16(sb + ALO + so, as2);  cp16(sb + ALO + so + 16, as2 + 8);
        const __nv_bfloat16* bs  = Bh + (long)(by*128 + lrow)*256 + k0 + lcg;
        const __nv_bfloat16* bs2 = Bl + (long)(by*128 + lrow)*256 + k0 + lcg;
        cp16(sb + BHI + so, bs);   cp16(sb + BHI + so + 16, bs + 8);
        cp16(sb + BLO + so, bs2);  cp16(sb + BLO + so + 16, bs2 + 8);
        cp_commit();
    };

    prefetch(0, 0);
    for (int kb = 0; kb < 8; kb++){
        const int st = kb & 1;
        if (kb + 1 < 8){ prefetch(kb + 1, st ^ 1); cp_wait1(); }
        else           { cp_wait0(); }
        __syncthreads();
        uint32_t sbase = (uint32_t)__cvta_generic_to_shared(smem) + st*STB;
        #pragma unroll
        for (int ks = 0; ks < 2; ks++){
            uint32_t ah[2][4], al[2][4];
            const int acol = ks*16 + (lane >> 4)*8;
            #pragma unroll
            for (int mt = 0; mt < 2; mt++){
                uint32_t off = ((wm*32 + mt*16 + (lane & 15))*40 + acol)*2;
                ldsm4(ah[mt], sbase + AHI + off);
                ldsm4(al[mt], sbase + ALO + off);
            }
            #pragma unroll
            for (int np = 0; np < 4; np++){
                uint32_t bh[4], bl[4];
                const int nr = wn*64 + np*16 + (lane >> 4)*8 + (lane & 7);
                const int nc = ks*16 + ((lane >> 3) & 1)*8;
                uint32_t boff = (nr*40 + nc)*2;
                ldsm4(bh, sbase + BHI + boff);
                ldsm4(bl, sbase + BLO + boff);
                #pragma unroll
                for (int mt = 0; mt < 2; mt++)
                    #pragma unroll
                    for (int sub = 0; sub < 2; sub++){
                        float* c = acc[mt][np*2 + sub];
                        mma_bf16(c, ah[mt], bh[2*sub], bh[2*sub+1]);
                        mma_bf16(c, ah[mt], bl[2*sub], bl[2*sub+1]);
                        mma_bf16(c, al[mt], bh[2*sub], bh[2*sub+1]);
                    }
            }
        }
        __syncthreads();
    }

    const int g = lane >> 2, t4 = lane & 3, odd = lane & 1;
    const int cbase = by*128 + wn*64;
    const int rbase = bx*128 + wm*32 + g;

    if (mode == 0){
        #pragma unroll
        for (int mt = 0; mt < 2; mt++)
            #pragma unroll
            for (int half = 0; half < 2; half++){
                int row = rbase + mt*16 + half*8;
                #pragma unroll
                for (int nt = 0; nt < 8; nt++)
                    #pragma unroll
                    for (int q = 0; q < 2; q++){
                        int col = cbase + nt*8 + t4*2 + q;
                        float v = acc[mt][nt][half*2 + q] + bvec[col];
                        v = (v > 0.0f) ? v : 0.1f*v;
                        g_hidden[row*256 + col] = v;
                        split2(v, g_hid_h[row*256 + col], g_hid_l[row*256 + col]);
                    }
            }
    } else {
        // gx0 write + fused layer0 t=0 (h=0 -> gates = gx0 + b_hh0, c_old = 0)
        #pragma unroll
        for (int mt = 0; mt < 2; mt++){
            int r0 = rbase + mt*16;
            float e0a = g_ep[r0*2],     e1a = g_ep[r0*2+1];
            float e0b = g_ep[(r0+8)*2], e1b = g_ep[(r0+8)*2+1];
            #pragma unroll
            for (int nt = 0; nt < 8; nt++){
                int col0 = cbase + nt*8 + t4*2, col1 = col0 + 1;
                float w00 = g_Wih0ep[col0*2], w01 = g_Wih0ep[col0*2+1];
                float w10 = g_Wih0ep[col1*2], w11 = g_Wih0ep[col1*2+1];
                float bi0 = g_bih0p[col0], bi1 = g_bih0p[col1];
                float v0 = acc[mt][nt][0] + bi0 + e0a*w00 + e1a*w01;
                float v1 = acc[mt][nt][1] + bi1 + e0a*w10 + e1a*w11;
                float v2 = acc[mt][nt][2] + bi0 + e0b*w00 + e1b*w01;
                float v3 = acc[mt][nt][3] + bi1 + e0b*w10 + e1b*w11;
                g_gx0[r0*1024 + col0]     = v0;
                g_gx0[r0*1024 + col1]     = v1;
                g_gx0[(r0+8)*1024 + col0] = v2;
                g_gx0[(r0+8)*1024 + col1] = v3;
                float bh0 = g_bhh0p[col0], bh1 = g_bhh0p[col1];
                float c0 = v0 + bh0, c1 = v1 + bh1, c2 = v2 + bh0, c3 = v3 + bh1;
                float s0 = __shfl_xor_sync(0xffffffffu, c0, 1);
                float s1 = __shfl_xor_sync(0xffffffffu, c1, 1);
                float s2 = __shfl_xor_sync(0xffffffffu, c2, 1);
                float s3 = __shfl_xor_sync(0xffffffffu, c3, 1);
                float gi, gg, go;
                if (!odd){ gi = c0; gg = s0; go = s1; }
                else     { gi = s2; gg = c2; go = c3; }
                int cell = ((cbase + nt*8) >> 2) + (t4 >> 1);
                int row = r0 + odd*8;
                float cn = sigm(gi)*tanhf(gg);
                float h  = sigm(go)*tanhf(cn);
                g_c0[row*256 + cell] = cn;
                qpack(h, g_h0a[1][row*256 + cell], g_h0b[1][row*256 + cell]);
            }
        }
    }
}

// ---------------- int8 IMMA GEMM + fused LSTM (3-stage pipeline) ----------------
// tile 128(M) x 64(N), BK=64 bytes; modes: 2 layer0, 3 layer1, 4 fused
#define QAH 0
#define QAL 10240
#define QBH 20480
#define QBL 25600
#define QSTB 30720

__global__ void __launch_bounds__(256, 2)
imma_k(int mode, int pp, int tstep)
{
    extern __shared__ __align__(16) char smem[];
    const int tid = threadIdx.x, lane = tid & 31, w = tid >> 5;
    const int wm = w >> 1, wn = w & 1;
    const int bx = blockIdx.x;

    int m = mode, by = blockIdx.y, p = pp, t = tstep;
    if (mode == 4){
        if (by < 16){ m = 3; p = pp ^ 1; t = tstep - 1; }
        else        { m = 2; by -= 16; }
    }

    const int8_t *Aa, *Ab, *A2a = nullptr, *A2b = nullptr, *Ba, *Bb;
    const float *cw, *bias4v; float* cst; int8_t *oha, *ohb;
    int bpitch, nk;
    if (m == 2){
        Aa = g_h0a[p]; Ab = g_h0b[p]; Ba = g_Whh0qa; Bb = g_Whh0qb;
        cw = g_cwhh0; bias4v = g_bhh0p; cst = g_c0;
        oha = g_h0a[p^1]; ohb = g_h0b[p^1];
        bpitch = 256; nk = 4;
    } else {
        Aa = g_h0a[p^1]; Ab = g_h0b[p^1]; A2a = g_h2a[p]; A2b = g_h2b[p];
        Ba = g_W1qa; Bb = g_W1qb; cw = g_cw1; bias4v = g_bsum1p; cst = g_c1;
        oha = g_h2a[p^1]; ohb = g_h2b[p^1];
        bpitch = 512; nk = (t == 0) ? 4 : 8;
    }

    int hh[2][4][4], mm[2][4][4];
    #pragma unroll
    for (int i = 0; i < 2; i++)
        #pragma unroll
        for (int j = 0; j < 4; j++)
            #pragma unroll
            for (int q = 0; q < 4; q++){ hh[i][j][q] = 0; mm[i][j][q] = 0; }

    const int arow = tid >> 1, ac = (tid & 1) * 32;
    const int brow = tid >> 2, bc = (tid & 3) * 16;
    const long garow = bx*128 + arow;
    const long gbrow = by*64 + brow;

    auto prefetch = [&](int kb, int st){
        int k0 = kb * 64;
        const int8_t *pa = Aa, *pb = Ab; int kk = k0;
        if (k0 >= 256){ pa = A2a; pb = A2b; kk = k0 - 256; }
        char* sb = smem + st * QSTB;
        int ad = arow*80 + ac;
        cp16(sb + QAH + ad,      pa + garow*256 + kk + ac);
        cp16(sb + QAH + ad + 16, pa + garow*256 + kk + ac + 16);
        cp16(sb + QAL + ad,      pb + garow*256 + kk + ac);
        cp16(sb + QAL + ad + 16, pb + garow*256 + kk + ac + 16);
        int bd = brow*80 + bc;
        cp16(sb + QBH + bd, Ba + gbrow*bpitch + k0 + bc);
        cp16(sb + QBL + bd, Bb + gbrow*bpitch + k0 + bc);
        cp_commit();
    };

    // 3-stage pipeline: keep up to 2 chunk loads in flight behind the consumer
    prefetch(0, 0);
    if (nk > 1) prefetch(1, 1);
    int st = 0, pf = 2;
    for (int kb = 0; kb < nk; kb++){
        if (kb + 2 < nk){
            prefetch(kb + 2, pf);
            pf = (pf == 2) ? 0 : pf + 1;
            cp_wait2();
        } else if (kb + 1 < nk){
            cp_wait1();
        } else {
            cp_wait0();
        }
        __syncthreads();
        uint32_t sbase = (uint32_t)__cvta_generic_to_shared(smem) + st*QSTB;
        #pragma unroll
        for (int slab = 0; slab < 2; slab++){
            const int kbyte = slab*32 + (lane >> 4)*16;
            uint32_t aH[2][4], aL[2][4];
            #pragma unroll
            for (int mt = 0; mt < 2; mt++){
                uint32_t off = (wm*32 + mt*16 + (lane & 15))*80 + kbyte;
                ldsm4(aH[mt], sbase + QAH + off);
                ldsm4(aL[mt], sbase + QAL + off);
            }
            uint32_t bH[2][4], bL[2][4];
            #pragma unroll
            for (int nf2 = 0; nf2 < 2; nf2++){
                uint32_t boff = (wn*32 + nf2*16 + (lane >> 4)*8 + (lane & 7))*80
                              + slab*32 + ((lane >> 3) & 1)*16;
                ldsm4(bH[nf2], sbase + QBH + boff);
                ldsm4(bL[nf2], sbase + QBL + boff);
            }
            #pragma unroll
            for (int mt = 0; mt < 2; mt++)
                #pragma unroll
                for (int nf2 = 0; nf2 < 2; nf2++)
                    #pragma unroll
                    for (int sub = 0; sub < 2; sub++){
                        int nf = nf2*2 + sub;
                        imma8(hh[mt][nf], aH[mt], bH[nf2][2*sub], bH[nf2][2*sub+1]);
                        imma8(mm[mt][nf], aH[mt], bL[nf2][2*sub], bL[nf2][2*sub+1]);
                        imma8(mm[mt][nf], aL[mt], bH[nf2][2*sub], bH[nf2][2*sub+1]);
                    }
        }
        __syncthreads();
        st = (st == 2) ? 0 : st + 1;
    }

    // epilogue: fused LSTM cell
    const int g = lane >> 2, t4 = lane & 3, odd = lane & 1;
    const int cbase = by*64 + wn*32;
    const int rbase = bx*128 + wm*32 + g;

    #pragma unroll
    for (int mt = 0; mt < 2; mt++){
        int row = rbase + mt*16 + odd*8;
        #pragma unroll
        for (int nf = 0; nf < 4; nf++){
            int col0 = cbase + nf*8 + t4*2;
            float cs0 = cw[col0], cs1 = cw[col0 + 1];
            float c0 = cs0*fmaf(16384.0f, (float)hh[mt][nf][0], 128.0f*(float)mm[mt][nf][0]);
            float c1 = cs1*fmaf(16384.0f, (float)hh[mt][nf][1], 128.0f*(float)mm[mt][nf][1]);
            float c2 = cs0*fmaf(16384.0f, (float)hh[mt][nf][2], 128.0f*(float)mm[mt][nf][2]);
            float c3 = cs1*fmaf(16384.0f, (float)hh[mt][nf][3], 128.0f*(float)mm[mt][nf][3]);
            float s0 = __shfl_xor_sync(0xffffffffu, c0, 1);
            float s1 = __shfl_xor_sync(0xffffffffu, c1, 1);
            float s2 = __shfl_xor_sync(0xffffffffu, c2, 1);
            float s3 = __shfl_xor_sync(0xffffffffu, c3, 1);
            float gi, gf, gg, go;
            if (!odd){ gi = c0; gf = c1; gg = s0; go = s1; }
            else     { gi = s2; gf = s3; gg = c2; go = c3; }
            int cell = ((cbase + nf*8) >> 2) + (t4 >> 1);
            float4 bb = *(const float4*)&bias4v[cell*4];
            gi += bb.x; gf += bb.y; gg += bb.z; go += bb.w;
            if (m == 2){
                float4 gx = *(const float4*)&g_gx0[row*1024 + cell*4];
                gi += gx.x; gf += gx.y; gg += gx.z; go += gx.w;
            }
            float cold = cst[row*256 + cell];
            float cn = sigm(gf)*cold + sigm(gi)*tanhf(gg);
            float h  = sigm(go)*tanhf(cn);
            cst[row*256 + cell] = cn;
            qpack(h, oha[row*256 + cell], ohb[row*256 + cell]);
            if (m == 3) g_traj[(row*TT + t)*256 + cell] = h;
        }
    }
}

// ---------------- endpoint + confidence ----------------
__global__ void epconf_k(const float* __restrict__ Wep, const float* __restrict__ bep,
                         const float* __restrict__ Wconf, const float* __restrict__ bconf,
                         float* __restrict__ out){
    int row = blockIdx.x*8 + (threadIdx.x >> 5);
    int lane = threadIdx.x & 31;
    const float* h = g_hidden + row*256;
    float s0 = 0.f, s1 = 0.f, s2 = 0.f;
    #pragma unroll
    for (int i = 0; i < 8; i++){
        float v = h[lane + i*32];
        s0 += v * Wep[lane + i*32];
        s1 += v * Wep[256 + lane + i*32];
        s2 += v * Wconf[lane + i*32];
    }
    #pragma unroll
    for (int o = 16; o; o >>= 1){
        s0 += __shfl_xor_sync(0xffffffffu, s0, o);
        s1 += __shfl_xor_sync(0xffffffffu, s1, o);
        s2 += __shfl_xor_sync(0xffffffffu, s2, o);
    }
    if (lane == 0){
        float e0 = s0 + bep[0], e1 = s1 + bep[1];
        g_ep[row*2] = e0; g_ep[row*2+1] = e1;
        out[OUT_EP + row*2] = e0; out[OUT_EP + row*2 + 1] = e1;
        out[OUT_CONF + row] = s2 + bconf[0];
    }
}

// ---------------- final projection ----------------
__global__ void final_k(const float* __restrict__ Wop, const float* __restrict__ bop,
                        float* __restrict__ out){
    int rt = blockIdx.x*8 + (threadIdx.x >> 5);
    int lane = threadIdx.x & 31;
    const float* h = g_traj + rt*256;
    float s0 = 0.f, s1 = 0.f;
    #pragma unroll
    for (int i = 0; i < 8; i++){
        float v = h[lane + i*32];
        s0 += v * Wop[lane + i*32];
        s1 += v * Wop[256 + lane + i*32];
    }
    #pragma unroll
    for (int o = 16; o; o >>= 1){
        s0 += __shfl_xor_sync(0xffffffffu, s0, o);
        s1 += __shfl_xor_sync(0xffffffffu, s1, o);
    }
    if (lane == 0){
        out[rt*2]     = s0 + bop[0];
        out[rt*2 + 1] = s1 + bop[1];
    }
}

// ---------------- launch ----------------
extern "C" void kernel_launch(void* const* d_in, const int* in_sizes, int n_in,
                              void* d_out, int out_size){
    (void)in_sizes; (void)n_in; (void)out_size;
    const float* obs    = (const float*)d_in[0];
    const float* lanef  = (const float*)d_in[1];
    const float* ds     = (const float*)d_in[3];
    const float* W_hid  = (const float*)d_in[4];
    const float* b_hid  = (const float*)d_in[5];
    const float* W_ep   = (const float*)d_in[6];
    const float* b_ep   = (const float*)d_in[7];
    const float* W_conf = (const float*)d_in[8];
    const float* b_conf = (const float*)d_in[9];
    const float* W_ih0  = (const float*)d_in[10];
    const float* W_hh0  = (const float*)d_in[11];
    const float* b_ih0  = (const float*)d_in[12];
    const float* b_hh0  = (const float*)d_in[13];
    const float* W_ih1  = (const float*)d_in[14];
    const float* W_hh1  = (const float*)d_in[15];
    const float* b_ih1  = (const float*)d_in[16];
    const float* b_hh1  = (const float*)d_in[17];
    const float* W_op   = (const float*)d_in[18];
    const float* b_op   = (const float*)d_in[19];
    float* out = (float*)d_out;

    cudaFuncSetAttribute(gemm_k, cudaFuncAttributeMaxDynamicSharedMemorySize, 2*STB);
    cudaFuncSetAttribute(imma_k, cudaFuncAttributeMaxDynamicSharedMemorySize, 3*QSTB);

    prep_w<<<512, 256>>>(W_hid, W_ih0, b_ih0, b_hh0, b_ih1, b_hh1);
    prep_wq<<<256, 256>>>(W_hh0, W_ih1, W_hh1);
    prep_in<<<512, 256>>>(obs, lanef, ds);

    gemm_k<<<dim3(48, 2), 256, 2*STB>>>(0, b_hid);              // encoder
    epconf_k<<<768, 256>>>(W_ep, b_ep, W_conf, b_conf, out);    // endpoint + conf
    gemm_k<<<dim3(48, 8), 256, 2*STB>>>(1, nullptr);            // gx0 + layer0 t=0

    for (int t = 1; t < TT; t++){
        imma_k<<<dim3(48, 32), 256, 3*QSTB>>>(4, t & 1, t);     // layer1(t-1) + layer0(t)
    }
    imma_k<<<dim3(48, 16), 256, 3*QSTB>>>(3, (TT-1) & 1, TT-1); // layer1 t=29
    final_k<<<23040, 256>>>(W_op, b_op, out);
}

// round 10
// speedup vs baseline: 1.1666x; 1.1666x over previous
#include <cuda_runtime.h>
#include <cuda_bf16.h>
#include <stdint.h>
#include <math.h>

#define NR 6144
#define HD 256
#define G4 1024
#define TT 30
#define QS 16319.0f

// ---------------- static device scratch ----------------
__device__ __nv_bfloat16 g_comb_h[NR*HD], g_comb_l[NR*HD];
__device__ float         g_hidden[NR*HD];
__device__ __nv_bfloat16 g_hid_h[NR*HD], g_hid_l[NR*HD];
__device__ float         g_ep[NR*2];
__device__ float         g_gx0[NR*G4];
__device__ __nv_bfloat16 g_Whid_h[HD*HD], g_Whid_l[HD*HD];
__device__ __nv_bfloat16 g_Wih0_h[G4*HD], g_Wih0_l[G4*HD];
__device__ float g_Wih0ep[G4*2];
__device__ float g_bih0p[G4], g_bhh0p[G4], g_bsum1p[G4];
__device__ float g_c0[NR*HD], g_c1[NR*HD];
// int8 path
__device__ __align__(128) int8_t g_h0a[2][NR*HD], g_h0b[2][NR*HD];
__device__ __align__(128) int8_t g_h2a[2][NR*HD], g_h2b[2][NR*HD];
__device__ __align__(128) int8_t g_Whh0qa[G4*HD], g_Whh0qb[G4*HD];
__device__ __align__(128) int8_t g_W1qa[G4*512],  g_W1qb[G4*512];
__device__ float g_cwhh0[G4], g_cw1[G4];

#define OUT_CONF 368640
#define OUT_EP   374784

// ---------------- helpers ----------------
__device__ __forceinline__ void split2(float x, __nv_bfloat16& h, __nv_bfloat16& l){
    h = __float2bfloat16(x);
    l = __float2bfloat16(x - __bfloat162float(h));
}
__device__ __forceinline__ float sigm(float x){ return 1.0f/(1.0f+expf(-x)); }
__device__ __forceinline__ void qpack(float h, int8_t& a, int8_t& b){
    int hq = __float2int_rn(h * QS);
    int ha = (hq + 64) >> 7;
    a = (int8_t)ha; b = (int8_t)(hq - (ha << 7));
}
__device__ __forceinline__ void cp16(void* sdst, const void* gsrc){
    unsigned sa = (unsigned)__cvta_generic_to_shared(sdst);
    asm volatile("cp.async.cg.shared.global [%0], [%1], 16;\n" :: "r"(sa), "l"(gsrc));
}
__device__ __forceinline__ void cp_commit(){ asm volatile("cp.async.commit_group;\n"); }
__device__ __forceinline__ void cp_wait0(){ asm volatile("cp.async.wait_group 0;\n"); }
__device__ __forceinline__ void ldsm4(uint32_t* r, uint32_t a){
    asm volatile("ldmatrix.sync.aligned.m8n8.x4.shared.b16 {%0,%1,%2,%3},[%4];\n"
        : "=r"(r[0]), "=r"(r[1]), "=r"(r[2]), "=r"(r[3]) : "r"(a));
}
__device__ __forceinline__ void mma_bf16(float* c, const uint32_t* a, uint32_t b0, uint32_t b1){
    asm volatile("mma.sync.aligned.m16n8k16.row.col.f32.bf16.bf16.f32 "
        "{%0,%1,%2,%3},{%4,%5,%6,%7},{%8,%9},{%0,%1,%2,%3};\n"
        : "+f"(c[0]), "+f"(c[1]), "+f"(c[2]), "+f"(c[3])
        : "r"(a[0]), "r"(a[1]), "r"(a[2]), "r"(a[3]), "r"(b0), "r"(b1));
}
__device__ __forceinline__ void imma8(int* c, const uint32_t* a, uint32_t b0, uint32_t b1){
    asm volatile("mma.sync.aligned.m16n8k32.row.col.s32.s8.s8.s32 "
        "{%0,%1,%2,%3},{%4,%5,%6,%7},{%8,%9},{%0,%1,%2,%3};\n"
        : "+r"(c[0]), "+r"(c[1]), "+r"(c[2]), "+r"(c[3])
        : "r"(a[0]), "r"(a[1]), "r"(a[2]), "r"(a[3]), "r"(b0), "r"(b1));
}

// ---------------- prep ----------------
__global__ void prep_w(const float* __restrict__ Whid, const float* __restrict__ Wih0,
                       const float* __restrict__ bih0, const float* __restrict__ bhh0,
                       const float* __restrict__ bih1, const float* __restrict__ bhh1){
    const int T0 = 65536, T1 = T0 + 262144, T2 = T1 + 1024;
    for (int i = blockIdx.x*blockDim.x + threadIdx.x; i < T2; i += gridDim.x*blockDim.x){
        if (i < T0){
            split2(Whid[i], g_Whid_h[i], g_Whid_l[i]);
        } else if (i < T1){
            int j = i - T0; int p = j >> 8, k = j & 255;
            int sr = (p & 3)*256 + (p >> 2);
            split2(Wih0[sr*258 + k], g_Wih0_h[j], g_Wih0_l[j]);
        } else {
            int p = i - T1;
            int sr = (p & 3)*256 + (p >> 2);
            g_bih0p[p]  = bih0[sr];
            g_bhh0p[p]  = bhh0[sr];
            g_bsum1p[p] = bih1[sr] + bhh1[sr];
            g_Wih0ep[p*2]   = Wih0[sr*258 + 256];
            g_Wih0ep[p*2+1] = Wih0[sr*258 + 257];
        }
    }
}

__global__ void prep_wq(const float* __restrict__ Whh0, const float* __restrict__ Wih1,
                        const float* __restrict__ Whh1){
    int task = blockIdx.x*8 + (threadIdx.x >> 5);
    int lane = threadIdx.x & 31;
    if (task >= 2048) return;
    bool isW1 = task >= 1024;
    int p  = isW1 ? task - 1024 : task;
    int sr = (p & 3)*256 + (p >> 2);
    int K  = isW1 ? 512 : 256;
    float mx = 0.0f;
    for (int k = lane; k < K; k += 32){
        float w = isW1 ? (k < 256 ? Wih1[sr*256 + k] : Whh1[sr*256 + (k - 256)])
                       : Whh0[sr*256 + k];
        mx = fmaxf(mx, fabsf(w));
    }
    #pragma unroll
    for (int o = 16; o; o >>= 1) mx = fmaxf(mx, __shfl_xor_sync(0xffffffffu, mx, o));
    float scale = QS / fmaxf(mx, 1e-20f);
    for (int k = lane; k < K; k += 32){
        float w = isW1 ? (k < 256 ? Wih1[sr*256 + k] : Whh1[sr*256 + (k - 256)])
                       : Whh0[sr*256 + k];
        int q = __float2int_rn(w * scale);
        int a = (q + 64) >> 7;
        int b = q - (a << 7);
        if (isW1){ g_W1qa[p*512 + k] = (int8_t)a; g_W1qb[p*512 + k] = (int8_t)b; }
        else     { g_Whh0qa[p*256 + k] = (int8_t)a; g_Whh0qb[p*256 + k] = (int8_t)b; }
    }
    if (lane == 0){
        float c = mx / (QS * QS);
        if (isW1) g_cw1[p] = c; else g_cwhh0[p] = c;
    }
}

__global__ void prep_in(const float* __restrict__ obs, const float* __restrict__ lanef,
                        const float* __restrict__ ds, const float* __restrict__ bop,
                        float* __restrict__ out){
    for (int idx = blockIdx.x*blockDim.x + threadIdx.x; idx < NR*HD; idx += gridDim.x*blockDim.x){
        int row = idx >> 8, col = idx & 255;
        int b = row / 6, kk = row - b*6;
        float v;
        if (col < 128)      v = obs[b*128 + col];
        else if (col < 192) v = lanef[b*64 + (col - 128)];
        else                v = ds[kk*64 + (col - 192)];
        split2(v, g_comb_h[idx], g_comb_l[idx]);
        g_c1[idx] = 0.0f;
        if (idx < OUT_CONF) out[idx] = bop[idx & 1];   // seed final outputs with bias
    }
}

// ---------------- bf16 split GEMM: 0=encoder, 1=gx0 (+fused layer0 t=0) ----------------
#define AHI 0
#define ALO 10240
#define BHI 20480
#define BLO 30720
#define STB 40960

__global__ void __launch_bounds__(256, 2)
gemm_k(int mode, const float* __restrict__ bvec)
{
    extern __shared__ __align__(16) char smem[];
    const int tid = threadIdx.x, lane = tid & 31, w = tid >> 5;
    const int wm = w >> 1, wn = w & 1;
    const int bx = blockIdx.x, by = blockIdx.y;

    const __nv_bfloat16 *Ah, *Al, *Bh, *Bl;
    if (mode == 0){ Ah=g_comb_h; Al=g_comb_l; Bh=g_Whid_h; Bl=g_Whid_l; }
    else          { Ah=g_hid_h;  Al=g_hid_l;  Bh=g_Wih0_h; Bl=g_Wih0_l; }

    float acc[2][8][4];
    #pragma unroll
    for (int i = 0; i < 2; i++)
        #pragma unroll
        for (int j = 0; j < 8; j++)
            #pragma unroll
            for (int q = 0; q < 4; q++) acc[i][j][q] = 0.0f;

    const int lrow = tid >> 1, lcg = (tid & 1) * 16;

    auto prefetch = [&](int kb, int st){
        int k0 = kb * 32;
        char* sb = smem + st * STB;
        const __nv_bfloat16* as  = Ah + (bx*128 + lrow)*256 + k0 + lcg;
        const __nv_bfloat16* as2 = Al + (bx*128 + lrow)*256 + k0 + lcg;
        int so = (lrow*40 + lcg)*2;
        cp16(sb + AHI + so, as);   cp16(sb + AHI + so + 16, as + 8);
        cp16(sb + ALO + so, as2);  cp16(sb + ALO + so + 16, as2 + 8);
        const __nv_bfloat16* bs  = Bh + (long)(by*128 + lrow)*256 + k0 + lcg;
        const __nv_bfloat16* bs2 = Bl + (long)(by*128 + lrow)*256 + k0 + lcg;
        cp16(sb + BHI + so, bs);   cp16(sb + BHI + so + 16, bs + 8);
        cp16(sb + BLO + so, bs2);  cp16(sb + BLO + so + 16, bs2 + 8);
        cp_commit();
    };

    prefetch(0, 0);
    for (int kb = 0; kb < 8; kb++){
        const int st = kb & 1;
        cp_wait0();
        __syncthreads();           // stage st ready AND stage st^1 fully consumed
        if (kb + 1 < 8) prefetch(kb + 1, st ^ 1);
        uint32_t sbase = (uint32_t)__cvta_generic_to_shared(smem) + st*STB;
        #pragma unroll
        for (int ks = 0; ks < 2; ks++){
            uint32_t ah[2][4], al[2][4];
            const int acol = ks*16 + (lane >> 4)*8;
            #pragma unroll
            for (int mt = 0; mt < 2; mt++){
                uint32_t off = ((wm*32 + mt*16 + (lane & 15))*40 + acol)*2;
                ldsm4(ah[mt], sbase + AHI + off);
                ldsm4(al[mt], sbase + ALO + off);
            }
            #pragma unroll
            for (int np = 0; np < 4; np++){
                uint32_t bh[4], bl[4];
                const int nr = wn*64 + np*16 + (lane >> 4)*8 + (lane & 7);
                const int nc = ks*16 + ((lane >> 3) & 1)*8;
                uint32_t boff = (nr*40 + nc)*2;
                ldsm4(bh, sbase + BHI + boff);
                ldsm4(bl, sbase + BLO + boff);
                #pragma unroll
                for (int mt = 0; mt < 2; mt++)
                    #pragma unroll
                    for (int sub = 0; sub < 2; sub++){
                        float* c = acc[mt][np*2 + sub];
                        mma_bf16(c, ah[mt], bh[2*sub], bh[2*sub+1]);
                        mma_bf16(c, ah[mt], bl[2*sub], bl[2*sub+1]);
                        mma_bf16(c, al[mt], bh[2*sub], bh[2*sub+1]);
                    }
            }
        }
    }

    const int g = lane >> 2, t4 = lane & 3, odd = lane & 1;
    const int cbase = by*128 + wn*64;
    const int rbase = bx*128 + wm*32 + g;

    if (mode == 0){
        #pragma unroll
        for (int mt = 0; mt < 2; mt++)
            #pragma unroll
            for (int half = 0; half < 2; half++){
                int row = rbase + mt*16 + half*8;
                #pragma unroll
                for (int nt = 0; nt < 8; nt++)
                    #pragma unroll
                    for (int q = 0; q < 2; q++){
                        int col = cbase + nt*8 + t4*2 + q;
                        float v = acc[mt][nt][half*2 + q] + bvec[col];
                        v = (v > 0.0f) ? v : 0.1f*v;
                        g_hidden[row*256 + col] = v;
                        split2(v, g_hid_h[row*256 + col], g_hid_l[row*256 + col]);
                    }
            }
    } else {
        // gx0 write + fused layer0 t=0 (h=0 -> gates = gx0 + b_hh0, c_old = 0)
        #pragma unroll
        for (int mt = 0; mt < 2; mt++){
            int r0 = rbase + mt*16;
            float e0a = g_ep[r0*2],     e1a = g_ep[r0*2+1];
            float e0b = g_ep[(r0+8)*2], e1b = g_ep[(r0+8)*2+1];
            #pragma unroll
            for (int nt = 0; nt < 8; nt++){
                int col0 = cbase + nt*8 + t4*2, col1 = col0 + 1;
                float w00 = g_Wih0ep[col0*2], w01 = g_Wih0ep[col0*2+1];
                float w10 = g_Wih0ep[col1*2], w11 = g_Wih0ep[col1*2+1];
                float bi0 = g_bih0p[col0], bi1 = g_bih0p[col1];
                float v0 = acc[mt][nt][0] + bi0 + e0a*w00 + e1a*w01;
                float v1 = acc[mt][nt][1] + bi1 + e0a*w10 + e1a*w11;
                float v2 = acc[mt][nt][2] + bi0 + e0b*w00 + e1b*w01;
                float v3 = acc[mt][nt][3] + bi1 + e0b*w10 + e1b*w11;
                g_gx0[r0*1024 + col0]     = v0;
                g_gx0[r0*1024 + col1]     = v1;
                g_gx0[(r0+8)*1024 + col0] = v2;
                g_gx0[(r0+8)*1024 + col1] = v3;
                float bh0 = g_bhh0p[col0], bh1 = g_bhh0p[col1];
                float c0 = v0 + bh0, c1 = v1 + bh1, c2 = v2 + bh0, c3 = v3 + bh1;
                float s0 = __shfl_xor_sync(0xffffffffu, c0, 1);
                float s1 = __shfl_xor_sync(0xffffffffu, c1, 1);
                float s2 = __shfl_xor_sync(0xffffffffu, c2, 1);
                float s3 = __shfl_xor_sync(0xffffffffu, c3, 1);
                float gi, gg, go;
                if (!odd){ gi = c0; gg = s0; go = s1; }
                else     { gi = s2; gg = c2; go = c3; }
                int cell = ((cbase + nt*8) >> 2) + (t4 >> 1);
                int row = r0 + odd*8;
                float cn = sigm(gi)*tanhf(gg);
                float h  = sigm(go)*tanhf(cn);
                g_c0[row*256 + cell] = cn;
                qpack(h, g_h0a[1][row*256 + cell], g_h0b[1][row*256 + cell]);
            }
        }
    }
}

// ---------------- int8 IMMA GEMM + fused LSTM (2-stage, single sync/chunk) ----------------
// tile 128(M) x 64(N), BK=64 bytes; modes: 2 layer0, 3 layer1, 4 fused
#define QAH 0
#define QAL 10240
#define QBH 20480
#define QBL 25600
#define QSTB 30720

__global__ void __launch_bounds__(256, 2)
imma_k(int mode, int pp, int tstep, const float* __restrict__ Wop, float* __restrict__ out)
{
    extern __shared__ __align__(16) char smem[];
    const int tid = threadIdx.x, lane = tid & 31, w = tid >> 5;
    const int wm = w >> 1, wn = w & 1;
    const int bx = blockIdx.x;

    int m = mode, by = blockIdx.y, p = pp, t = tstep;
    if (mode == 4){
        if (by < 16){ m = 3; p = pp ^ 1; t = tstep - 1; }
        else        { m = 2; by -= 16; }
    }

    const int8_t *Aa, *Ab, *A2a = nullptr, *A2b = nullptr, *Ba, *Bb;
    const float *cw, *bias4v; float* cst; int8_t *oha, *ohb;
    int bpitch, nk;
    if (m == 2){
        Aa = g_h0a[p]; Ab = g_h0b[p]; Ba = g_Whh0qa; Bb = g_Whh0qb;
        cw = g_cwhh0; bias4v = g_bhh0p; cst = g_c0;
        oha = g_h0a[p^1]; ohb = g_h0b[p^1];
        bpitch = 256; nk = 4;
    } else {
        Aa = g_h0a[p^1]; Ab = g_h0b[p^1]; A2a = g_h2a[p]; A2b = g_h2b[p];
        Ba = g_W1qa; Bb = g_W1qb; cw = g_cw1; bias4v = g_bsum1p; cst = g_c1;
        oha = g_h2a[p^1]; ohb = g_h2b[p^1];
        bpitch = 512; nk = (t == 0) ? 4 : 8;
    }

    int hh[2][4][4], mm[2][4][4];
    #pragma unroll
    for (int i = 0; i < 2; i++)
        #pragma unroll
        for (int j = 0; j < 4; j++)
            #pragma unroll
            for (int q = 0; q < 4; q++){ hh[i][j][q] = 0; mm[i][j][q] = 0; }

    const int arow = tid >> 1, ac = (tid & 1) * 32;
    const int brow = tid >> 2, bc = (tid & 3) * 16;
    const long garow = bx*128 + arow;
    const long gbrow = by*64 + brow;

    auto prefetch = [&](int kb, int st){
        int k0 = kb * 64;
        const int8_t *pa = Aa, *pb = Ab; int kk = k0;
        if (k0 >= 256){ pa = A2a; pb = A2b; kk = k0 - 256; }
        char* sb = smem + st * QSTB;
        int ad = arow*80 + ac;
        cp16(sb + QAH + ad,      pa + garow*256 + kk + ac);
        cp16(sb + QAH + ad + 16, pa + garow*256 + kk + ac + 16);
        cp16(sb + QAL + ad,      pb + garow*256 + kk + ac);
        cp16(sb + QAL + ad + 16, pb + garow*256 + kk + ac + 16);
        int bd = brow*80 + bc;
        cp16(sb + QBH + bd, Ba + gbrow*bpitch + k0 + bc);
        cp16(sb + QBL + bd, Bb + gbrow*bpitch + k0 + bc);
        cp_commit();
    };

    prefetch(0, 0);
    for (int kb = 0; kb < nk; kb++){
        const int st = kb & 1;
        cp_wait0();
        __syncthreads();          // stage st ready AND stage st^1 fully consumed
        if (kb + 1 < nk) prefetch(kb + 1, st ^ 1);
        uint32_t sbase = (uint32_t)__cvta_generic_to_shared(smem) + st*QSTB;
        #pragma unroll
        for (int slab = 0; slab < 2; slab++){
            const int kbyte = slab*32 + (lane >> 4)*16;
            uint32_t aH[2][4], aL[2][4];
            #pragma unroll
            for (int mt = 0; mt < 2; mt++){
                uint32_t off = (wm*32 + mt*16 + (lane & 15))*80 + kbyte;
                ldsm4(aH[mt], sbase + QAH + off);
                ldsm4(aL[mt], sbase + QAL + off);
            }
            uint32_t bH[2][4], bL[2][4];
            #pragma unroll
            for (int nf2 = 0; nf2 < 2; nf2++){
                uint32_t boff = (wn*32 + nf2*16 + (lane >> 4)*8 + (lane & 7))*80
                              + slab*32 + ((lane >> 3) & 1)*16;
                ldsm4(bH[nf2], sbase + QBH + boff);
                ldsm4(bL[nf2], sbase + QBL + boff);
            }
            #pragma unroll
            for (int mt = 0; mt < 2; mt++)
                #pragma unroll
                for (int nf2 = 0; nf2 < 2; nf2++)
                    #pragma unroll
                    for (int sub = 0; sub < 2; sub++){
                        int nf = nf2*2 + sub;
                        imma8(hh[mt][nf], aH[mt], bH[nf2][2*sub], bH[nf2][2*sub+1]);
                        imma8(mm[mt][nf], aH[mt], bL[nf2][2*sub], bL[nf2][2*sub+1]);
                        imma8(mm[mt][nf], aL[mt], bH[nf2][2*sub], bH[nf2][2*sub+1]);
                    }
        }
    }

    // epilogue: fused LSTM cell (+ fused W_op projection for layer1)
    const int g = lane >> 2, t4 = lane & 3, odd = lane & 1;
    const int cbase = by*64 + wn*32;
    const int rbase = bx*128 + wm*32 + g;

    #pragma unroll
    for (int mt = 0; mt < 2; mt++){
        int row = rbase + mt*16 + odd*8;
        float s0 = 0.0f, s1 = 0.0f;
        #pragma unroll
        for (int nf = 0; nf < 4; nf++){
            int col0 = cbase + nf*8 + t4*2;
            float cs0 = cw[col0], cs1 = cw[col0 + 1];
            float c0 = cs0*fmaf(16384.0f, (float)hh[mt][nf][0], 128.0f*(float)mm[mt][nf][0]);
            float c1 = cs1*fmaf(16384.0f, (float)hh[mt][nf][1], 128.0f*(float)mm[mt][nf][1]);
            float c2 = cs0*fmaf(16384.0f, (float)hh[mt][nf][2], 128.0f*(float)mm[mt][nf][2]);
            float c3 = cs1*fmaf(16384.0f, (float)hh[mt][nf][3], 128.0f*(float)mm[mt][nf][3]);
            float sh0 = __shfl_xor_sync(0xffffffffu, c0, 1);
            float sh1 = __shfl_xor_sync(0xffffffffu, c1, 1);
            float sh2 = __shfl_xor_sync(0xffffffffu, c2, 1);
            float sh3 = __shfl_xor_sync(0xffffffffu, c3, 1);
            float gi, gf, gg, go;
            if (!odd){ gi = c0; gf = c1; gg = sh0; go = sh1; }
            else     { gi = sh2; gf = sh3; gg = c2; go = c3; }
            int cell = ((cbase + nf*8) >> 2) + (t4 >> 1);
            float4 bb = *(const float4*)&bias4v[cell*4];
            gi += bb.x; gf += bb.y; gg += bb.z; go += bb.w;
            if (m == 2){
                float4 gx = *(const float4*)&g_gx0[row*1024 + cell*4];
                gi += gx.x; gf += gx.y; gg += gx.z; go += gx.w;
            }
            float cold = cst[row*256 + cell];
            float cn = sigm(gf)*cold + sigm(gi)*tanhf(gg);
            float h  = sigm(go)*tanhf(cn);
            cst[row*256 + cell] = cn;
            qpack(h, oha[row*256 + cell], ohb[row*256 + cell]);
            if (m == 3){
                s0 = fmaf(h, Wop[cell], s0);
                s1 = fmaf(h, Wop[256 + cell], s1);
            }
        }
        if (m == 3){
            int rt = row*TT + t;
            atomicAdd(&out[rt*2],     s0);
            atomicAdd(&out[rt*2 + 1], s1);
        }
    }
}

// ---------------- endpoint + confidence ----------------
__global__ void epconf_k(const float* __restrict__ Wep, const float* __restrict__ bep,
                         const float* __restrict__ Wconf, const float* __restrict__ bconf,
                         float* __restrict__ out){
    int row = blockIdx.x*8 + (threadIdx.x >> 5);
    int lane = threadIdx.x & 31;
    const float* h = g_hidden + row*256;
    float s0 = 0.f, s1 = 0.f, s2 = 0.f;
    #pragma unroll
    for (int i = 0; i < 8; i++){
        float v = h[lane + i*32];
        s0 += v * Wep[lane + i*32];
        s1 += v * Wep[256 + lane + i*32];
        s2 += v * Wconf[lane + i*32];
    }
    #pragma unroll
    for (int o = 16; o; o >>= 1){
        s0 += __shfl_xor_sync(0xffffffffu, s0, o);
        s1 += __shfl_xor_sync(0xffffffffu, s1, o);
        s2 += __shfl_xor_sync(0xffffffffu, s2, o);
    }
    if (lane == 0){
        float e0 = s0 + bep[0], e1 = s1 + bep[1];
        g_ep[row*2] = e0; g_ep[row*2+1] = e1;
        out[OUT_EP + row*2] = e0; out[OUT_EP + row*2 + 1] = e1;
        out[OUT_CONF + row] = s2 + bconf[0];
    }
}

// ---------------- launch ----------------
extern "C" void kernel_launch(void* const* d_in, const int* in_sizes, int n_in,
                              void* d_out, int out_size){
    (void)in_sizes; (void)n_in; (void)out_size;
    const float* obs    = (const float*)d_in[0];
    const float* lanef  = (const float*)d_in[1];
    const float* ds     = (const float*)d_in[3];
    const float* W_hid  = (const float*)d_in[4];
    const float* b_hid  = (const float*)d_in[5];
    const float* W_ep   = (const float*)d_in[6];
    const float* b_ep   = (const float*)d_in[7];
    const float* W_conf = (const float*)d_in[8];
    const float* b_conf = (const float*)d_in[9];
    const float* W_ih0  = (const float*)d_in[10];
    const float* W_hh0  = (const float*)d_in[11];
    const float* b_ih0  = (const float*)d_in[12];
    const float* b_hh0  = (const float*)d_in[13];
    const float* W_ih1  = (const float*)d_in[14];
    const float* W_hh1  = (const float*)d_in[15];
    const float* b_ih1  = (const float*)d_in[16];
    const float* b_hh1  = (const float*)d_in[17];
    const float* W_op   = (const float*)d_in[18];
    const float* b_op   = (const float*)d_in[19];
    float* out = (float*)d_out;

    cudaFuncSetAttribute(gemm_k, cudaFuncAttributeMaxDynamicSharedMemorySize, 2*STB);
    cudaFuncSetAttribute(imma_k, cudaFuncAttributeMaxDynamicSharedMemorySize, 2*QSTB);

    prep_w<<<512, 256>>>(W_hid, W_ih0, b_ih0, b_hh0, b_ih1, b_hh1);
    prep_wq<<<256, 256>>>(W_hh0, W_ih1, W_hh1);
    prep_in<<<512, 256>>>(obs, lanef, ds, b_op, out);

    gemm_k<<<dim3(48, 2), 256, 2*STB>>>(0, b_hid);              // encoder
    epconf_k<<<768, 256>>>(W_ep, b_ep, W_conf, b_conf, out);    // endpoint + conf
    gemm_k<<<dim3(48, 8), 256, 2*STB>>>(1, nullptr);            // gx0 + layer0 t=0

    for (int t = 1; t < TT; t++){
        imma_k<<<dim3(48, 32), 256, 2*QSTB>>>(4, t & 1, t, W_op, out); // layer1(t-1)+layer0(t)
    }
    imma_k<<<dim3(48, 16), 256, 2*QSTB>>>(3, (TT-1) & 1, TT-1, W_op, out); // layer1 t=29
}

// round 11
// speedup vs baseline: 1.1932x; 1.0228x over previous
#include <cuda_runtime.h>
#include <cuda_bf16.h>
#include <stdint.h>
#include <math.h>

#define NR 6144
#define HD 256
#define G4 1024
#define TT 30
#define QS 16319.0f

// ---------------- static device scratch ----------------
__device__ __nv_bfloat16 g_comb_h[NR*HD], g_comb_l[NR*HD];
__device__ float         g_hidden[NR*HD];
__device__ __nv_bfloat16 g_hid_h[NR*HD], g_hid_l[NR*HD];
__device__ float         g_ep[NR*2];
__device__ float         g_gx0[NR*G4];
__device__ __nv_bfloat16 g_Whid_h[HD*HD], g_Whid_l[HD*HD];
__device__ __nv_bfloat16 g_Wih0_h[G4*HD], g_Wih0_l[G4*HD];
__device__ float g_Wih0ep[G4*2];
__device__ float g_bih0p[G4], g_bhh0p[G4], g_bsum1p[G4];
__device__ float g_c0[NR*HD], g_c1[NR*HD];
// int8 path — TILED layouts (80B-pitch smem images, contiguous per (tile,kchunk))
// h-state: [bx(48)][kc(4)][row(128)][80]
#define HTILE (48*4*128*80)
__device__ __align__(128) int8_t g_h0a[2][HTILE], g_h0b[2][HTILE];
__device__ __align__(128) int8_t g_h2a[2][HTILE], g_h2b[2][HTILE];
// weights: Whh0 [by(16)][kc(4)][row(64)][80]; W1 [by(16)][kc(8)][row(64)][80]
__device__ __align__(128) int8_t g_Whh0qa[16*4*64*80], g_Whh0qb[16*4*64*80];
__device__ __align__(128) int8_t g_W1qa[16*8*64*80],  g_W1qb[16*8*64*80];
__device__ float g_cwhh0[G4], g_cw1[G4];

#define OUT_CONF 368640
#define OUT_EP   374784

// ---------------- helpers ----------------
__device__ __forceinline__ void split2(float x, __nv_bfloat16& h, __nv_bfloat16& l){
    h = __float2bfloat16(x);
    l = __float2bfloat16(x - __bfloat162float(h));
}
__device__ __forceinline__ float sigm(float x){ return 1.0f/(1.0f+expf(-x)); }
__device__ __forceinline__ void qpack(float h, int8_t& a, int8_t& b){
    int hq = __float2int_rn(h * QS);
    int ha = (hq + 64) >> 7;
    a = (int8_t)ha; b = (int8_t)(hq - (ha << 7));
}
// tiled h-state offset: row in [0,6144), c = K-position in [0,256)
__device__ __forceinline__ long hoff(int row, int c){
    return ((long)((row >> 7)*4 + (c >> 6))*128 + (row & 127))*80 + (c & 63);
}
__device__ __forceinline__ uint32_t smem_u32(const void* p){
    uint32_t a;
    asm("{ .reg .u64 t; cvta.to.shared.u64 t, %1; cvt.u32.u64 %0, t; }" : "=r"(a) : "l"(p));
    return a;
}
__device__ __forceinline__ void cp16(void* sdst, const void* gsrc){
    unsigned sa = (unsigned)__cvta_generic_to_shared(sdst);
    asm volatile("cp.async.cg.shared.global [%0], [%1], 16;\n" :: "r"(sa), "l"(gsrc));
}
__device__ __forceinline__ void cp_commit(){ asm volatile("cp.async.commit_group;\n"); }
__device__ __forceinline__ void cp_wait0(){ asm volatile("cp.async.wait_group 0;\n"); }
__device__ __forceinline__ void bulk_cp(uint32_t dst, const void* src, uint32_t bytes, uint32_t mbar){
    asm volatile("cp.async.bulk.shared::cluster.global.mbarrier::complete_tx::bytes [%0], [%1], %2, [%3];"
        :: "r"(dst), "l"(src), "r"(bytes), "r"(mbar) : "memory");
}
__device__ __forceinline__ void mbar_init(uint32_t a, uint32_t cnt){
    asm volatile("mbarrier.init.shared.b64 [%0], %1;" :: "r"(a), "r"(cnt) : "memory");
}
__device__ __forceinline__ void mbar_expect(uint32_t a, uint32_t bytes){
    asm volatile("mbarrier.arrive.expect_tx.shared.b64 _, [%0], %1;" :: "r"(a), "r"(bytes) : "memory");
}
#define MBAR_WAIT(mb, ph) do { \
    uint32_t _mb = (mb), _p = (ph), _done; \
    asm volatile("{\n\t.reg .pred p;\n\t" \
        "mbarrier.try_wait.parity.acquire.cta.shared::cta.b64 p, [%1], %2;\n\t" \
        "selp.b32 %0, 1, 0, p;\n\t}" : "=r"(_done) : "r"(_mb), "r"(_p) : "memory"); \
    if (!_done) { \
        asm volatile("{\n\t.reg .pred P1;\n\t" \
            "WL_%=:\n\t" \
            "mbarrier.try_wait.parity.acquire.cta.shared::cta.b64 P1, [%0], %1, 0x989680;\n\t" \
            "@P1 bra.uni WD_%=;\n\t" \
            "bra.uni WL_%=;\n\t" \
            "WD_%=:\n\t}" :: "r"(_mb), "r"(_p) : "memory"); \
    } \
} while(0)
__device__ __forceinline__ void ldsm4(uint32_t* r, uint32_t a){
    asm volatile("ldmatrix.sync.aligned.m8n8.x4.shared.b16 {%0,%1,%2,%3},[%4];\n"
        : "=r"(r[0]), "=r"(r[1]), "=r"(r[2]), "=r"(r[3]) : "r"(a));
}
__device__ __forceinline__ void mma_bf16(float* c, const uint32_t* a, uint32_t b0, uint32_t b1){
    asm volatile("mma.sync.aligned.m16n8k16.row.col.f32.bf16.bf16.f32 "
        "{%0,%1,%2,%3},{%4,%5,%6,%7},{%8,%9},{%0,%1,%2,%3};\n"
        : "+f"(c[0]), "+f"(c[1]), "+f"(c[2]), "+f"(c[3])
        : "r"(a[0]), "r"(a[1]), "r"(a[2]), "r"(a[3]), "r"(b0), "r"(b1));
}
__device__ __forceinline__ void imma8(int* c, const uint32_t* a, uint32_t b0, uint32_t b1){
    asm volatile("mma.sync.aligned.m16n8k32.row.col.s32.s8.s8.s32 "
        "{%0,%1,%2,%3},{%4,%5,%6,%7},{%8,%9},{%0,%1,%2,%3};\n"
        : "+r"(c[0]), "+r"(c[1]), "+r"(c[2]), "+r"(c[3])
        : "r"(a[0]), "r"(a[1]), "r"(a[2]), "r"(a[3]), "r"(b0), "r"(b1));
}

// ---------------- prep ----------------
__global__ void prep_w(const float* __restrict__ Whid, const float* __restrict__ Wih0,
                       const float* __restrict__ bih0, const float* __restrict__ bhh0,
                       const float* __restrict__ bih1, const float* __restrict__ bhh1){
    const int T0 = 65536, T1 = T0 + 262144, T2 = T1 + 1024;
    for (int i = blockIdx.x*blockDim.x + threadIdx.x; i < T2; i += gridDim.x*blockDim.x){
        if (i < T0){
            split2(Whid[i], g_Whid_h[i], g_Whid_l[i]);
        } else if (i < T1){
            int j = i - T0; int p = j >> 8, k = j & 255;
            int sr = (p & 3)*256 + (p >> 2);
            split2(Wih0[sr*258 + k], g_Wih0_h[j], g_Wih0_l[j]);
        } else {
            int p = i - T1;
            int sr = (p & 3)*256 + (p >> 2);
            g_bih0p[p]  = bih0[sr];
            g_bhh0p[p]  = bhh0[sr];
            g_bsum1p[p] = bih1[sr] + bhh1[sr];
            g_Wih0ep[p*2]   = Wih0[sr*258 + 256];
            g_Wih0ep[p*2+1] = Wih0[sr*258 + 257];
        }
    }
}

__global__ void prep_wq(const float* __restrict__ Whh0, const float* __restrict__ Wih1,
                        const float* __restrict__ Whh1){
    int task = blockIdx.x*8 + (threadIdx.x >> 5);
    int lane = threadIdx.x & 31;
    if (task >= 2048) return;
    bool isW1 = task >= 1024;
    int p  = isW1 ? task - 1024 : task;
    int sr = (p & 3)*256 + (p >> 2);
    int K  = isW1 ? 512 : 256;
    float mx = 0.0f;
    for (int k = lane; k < K; k += 32){
        float w = isW1 ? (k < 256 ? Wih1[sr*256 + k] : Whh1[sr*256 + (k - 256)])
                       : Whh0[sr*256 + k];
        mx = fmaxf(mx, fabsf(w));
    }
    #pragma unroll
    for (int o = 16; o; o >>= 1) mx = fmaxf(mx, __shfl_xor_sync(0xffffffffu, mx, o));
    float scale = QS / fmaxf(mx, 1e-20f);
    int nkc = isW1 ? 8 : 4;
    for (int k = lane; k < K; k += 32){
        float w = isW1 ? (k < 256 ? Wih1[sr*256 + k] : Whh1[sr*256 + (k - 256)])
                       : Whh0[sr*256 + k];
        int q = __float2int_rn(w * scale);
        int a = (q + 64) >> 7;
        int b = q - (a << 7);
        long off = ((long)((p >> 6)*nkc + (k >> 6))*64 + (p & 63))*80 + (k & 63);
        if (isW1){ g_W1qa[off] = (int8_t)a; g_W1qb[off] = (int8_t)b; }
        else     { g_Whh0qa[off] = (int8_t)a; g_Whh0qb[off] = (int8_t)b; }
    }
    if (lane == 0){
        float c = mx / (QS * QS);
        if (isW1) g_cw1[p] = c; else g_cwhh0[p] = c;
    }
}

__global__ void prep_in(const float* __restrict__ obs, const float* __restrict__ lanef,
                        const float* __restrict__ ds, const float* __restrict__ bop,
                        float* __restrict__ out){
    for (int idx = blockIdx.x*blockDim.x + threadIdx.x; idx < NR*HD; idx += gridDim.x*blockDim.x){
        int row = idx >> 8, col = idx & 255;
        int b = row / 6, kk = row - b*6;
        float v;
        if (col < 128)      v = obs[b*128 + col];
        else if (col < 192) v = lanef[b*64 + (col - 128)];
        else                v = ds[kk*64 + (col - 192)];
        split2(v, g_comb_h[idx], g_comb_l[idx]);
        g_c1[idx] = 0.0f;
        if (idx < OUT_CONF) out[idx] = bop[idx & 1];   // seed final outputs with bias
    }
}

// ---------------- bf16 split GEMM: 0=encoder, 1=gx0 (+fused layer0 t=0) ----------------
#define AHI 0
#define ALO 10240
#define BHI 20480
#define BLO 30720
#define STB 40960

__global__ void __launch_bounds__(256, 2)
gemm_k(int mode, const float* __restrict__ bvec)
{
    extern __shared__ __align__(128) char smem[];
    const int tid = threadIdx.x, lane = tid & 31, w = tid >> 5;
    const int wm = w >> 1, wn = w & 1;
    const int bx = blockIdx.x, by = blockIdx.y;

    const __nv_bfloat16 *Ah, *Al, *Bh, *Bl;
    if (mode == 0){ Ah=g_comb_h; Al=g_comb_l; Bh=g_Whid_h; Bl=g_Whid_l; }
    else          { Ah=g_hid_h;  Al=g_hid_l;  Bh=g_Wih0_h; Bl=g_Wih0_l; }

    float acc[2][8][4];
    #pragma unroll
    for (int i = 0; i < 2; i++)
        #pragma unroll
        for (int j = 0; j < 8; j++)
            #pragma unroll
            for (int q = 0; q < 4; q++) acc[i][j][q] = 0.0f;

    const int lrow = tid >> 1, lcg = (tid & 1) * 16;

    auto prefetch = [&](int kb, int st){
        int k0 = kb * 32;
        char* sb = smem + st * STB;
        const __nv_bfloat16* as  = Ah + (bx*128 + lrow)*256 + k0 + lcg;
        const __nv_bfloat16* as2 = Al + (bx*128 + lrow)*256 + k0 + lcg;
        int so = (lrow*40 + lcg)*2;
        cp16(sb + AHI + so, as);   cp16(sb + AHI + so + 16, as + 8);
        cp16(sb + ALO + so, as2);  cp16(sb + ALO + so + 16, as2 + 8);
        const __nv_bfloat16* bs  = Bh + (long)(by*128 + lrow)*256 + k0 + lcg;
        const __nv_bfloat16* bs2 = Bl + (long)(by*128 + lrow)*256 + k0 + lcg;
        cp16(sb + BHI + so, bs);   cp16(sb + BHI + so + 16, bs + 8);
        cp16(sb + BLO + so, bs2);  cp16(sb + BLO + so + 16, bs2 + 8);
        cp_commit();
    };

    prefetch(0, 0);
    for (int kb = 0; kb < 8; kb++){
        const int st = kb & 1;
        cp_wait0();
        __syncthreads();
        if (kb + 1 < 8) prefetch(kb + 1, st ^ 1);
        uint32_t sbase = (uint32_t)__cvta_generic_to_shared(smem) + st*STB;
        #pragma unroll
        for (int ks = 0; ks < 2; ks++){
            uint32_t ah[2][4], al[2][4];
            const int acol = ks*16 + (lane >> 4)*8;
            #pragma unroll
            for (int mt = 0; mt < 2; mt++){
                uint32_t off = ((wm*32 + mt*16 + (lane & 15))*40 + acol)*2;
                ldsm4(ah[mt], sbase + AHI + off);
                ldsm4(al[mt], sbase + ALO + off);
            }
            #pragma unroll
            for (int np = 0; np < 4; np++){
                uint32_t bh[4], bl[4];
                const int nr = wn*64 + np*16 + (lane >> 4)*8 + (lane & 7);
                const int nc = ks*16 + ((lane >> 3) & 1)*8;
                uint32_t boff = (nr*40 + nc)*2;
                ldsm4(bh, sbase + BHI + boff);
                ldsm4(bl, sbase + BLO + boff);
                #pragma unroll
                for (int mt = 0; mt < 2; mt++)
                    #pragma unroll
                    for (int sub = 0; sub < 2; sub++){
                        float* c = acc[mt][np*2 + sub];
                        mma_bf16(c, ah[mt], bh[2*sub], bh[2*sub+1]);
                        mma_bf16(c, ah[mt], bl[2*sub], bl[2*sub+1]);
                        mma_bf16(c, al[mt], bh[2*sub], bh[2*sub+1]);
                    }
            }
        }
    }

    const int g = lane >> 2, t4 = lane & 3, odd = lane & 1;
    const int cbase = by*128 + wn*64;
    const int rbase = bx*128 + wm*32 + g;

    if (mode == 0){
        #pragma unroll
        for (int mt = 0; mt < 2; mt++)
            #pragma unroll
            for (int half = 0; half < 2; half++){
                int row = rbase + mt*16 + half*8;
                #pragma unroll
                for (int nt = 0; nt < 8; nt++)
                    #pragma unroll
                    for (int q = 0; q < 2; q++){
                        int col = cbase + nt*8 + t4*2 + q;
                        float v = acc[mt][nt][half*2 + q] + bvec[col];
                        v = (v > 0.0f) ? v : 0.1f*v;
                        g_hidden[row*256 + col] = v;
                        split2(v, g_hid_h[row*256 + col], g_hid_l[row*256 + col]);
                    }
            }
    } else {
        // gx0 write + fused layer0 t=0 (h=0 -> gates = gx0 + b_hh0, c_old = 0)
        #pragma unroll
        for (int mt = 0; mt < 2; mt++){
            int r0 = rbase + mt*16;
            float e0a = g_ep[r0*2],     e1a = g_ep[r0*2+1];
            float e0b = g_ep[(r0+8)*2], e1b = g_ep[(r0+8)*2+1];
            #pragma unroll
            for (int nt = 0; nt < 8; nt++){
                int col0 = cbase + nt*8 + t4*2, col1 = col0 + 1;
                float w00 = g_Wih0ep[col0*2], w01 = g_Wih0ep[col0*2+1];
                float w10 = g_Wih0ep[col1*2], w11 = g_Wih0ep[col1*2+1];
                float bi0 = g_bih0p[col0], bi1 = g_bih0p[col1];
                float v0 = acc[mt][nt][0] + bi0 + e0a*w00 + e1a*w01;
                float v1 = acc[mt][nt][1] + bi1 + e0a*w10 + e1a*w11;
                float v2 = acc[mt][nt][2] + bi0 + e0b*w00 + e1b*w01;
                float v3 = acc[mt][nt][3] + bi1 + e0b*w10 + e1b*w11;
                g_gx0[r0*1024 + col0]     = v0;
                g_gx0[r0*1024 + col1]     = v1;
                g_gx0[(r0+8)*1024 + col0] = v2;
                g_gx0[(r0+8)*1024 + col1] = v3;
                float bh0 = g_bhh0p[col0], bh1 = g_bhh0p[col1];
                float c0 = v0 + bh0, c1 = v1 + bh1, c2 = v2 + bh0, c3 = v3 + bh1;
                float s0 = __shfl_xor_sync(0xffffffffu, c0, 1);
                float s1 = __shfl_xor_sync(0xffffffffu, c1, 1);
                float s2 = __shfl_xor_sync(0xffffffffu, c2, 1);
                float s3 = __shfl_xor_sync(0xffffffffu, c3, 1);
                float gi, gg, go;
                if (!odd){ gi = c0; gg = s0; go = s1; }
                else     { gi = s2; gg = c2; go = c3; }
                int cell = ((cbase + nt*8) >> 2) + (t4 >> 1);
                int row = r0 + odd*8;
                float cn = sigm(gi)*tanhf(gg);
                float h  = sigm(go)*tanhf(cn);
                g_c0[row*256 + cell] = cn;
                long off = hoff(row, cell);
                qpack(h, g_h0a[1][off], g_h0b[1][off]);
            }
        }
    }
}

// ---------------- int8 IMMA GEMM + fused LSTM (bulk-copy pipeline) ----------------
#define QAH 0
#define QAL 10240
#define QBH 20480
#define QBL 25600
#define QSTB 30720

__global__ void __launch_bounds__(256, 2)
imma_k(int mode, int pp, int tstep, const float* __restrict__ Wop, float* __restrict__ out)
{
    extern __shared__ __align__(128) char smem[];
    __shared__ __align__(8) uint64_t mbars[2];
    const uint32_t sb = smem_u32(smem);
    const uint32_t mb0 = smem_u32(&mbars[0]);
    const int tid = threadIdx.x, lane = tid & 31, w = tid >> 5;
    const int wm = w >> 1, wn = w & 1;
    const int bx = blockIdx.x;

    int m = mode, by = blockIdx.y, p = pp, t = tstep;
    if (mode == 4){
        if (by < 16){ m = 3; p = pp ^ 1; t = tstep - 1; }
        else        { m = 2; by -= 16; }
    }

    const int8_t *Aa, *Ab, *A2a = nullptr, *A2b = nullptr, *Ba, *Bb;
    const float *cw, *bias4v; float* cst; int8_t *oha, *ohb;
    int nk;
    if (m == 2){
        Aa = g_h0a[p]; Ab = g_h0b[p];
        Ba = g_Whh0qa + (long)by*4*5120; Bb = g_Whh0qb + (long)by*4*5120;
        cw = g_cwhh0; bias4v = g_bhh0p; cst = g_c0;
        oha = g_h0a[p^1]; ohb = g_h0b[p^1];
        nk = 4;
    } else {
        Aa = g_h0a[p^1]; Ab = g_h0b[p^1]; A2a = g_h2a[p]; A2b = g_h2b[p];
        Ba = g_W1qa + (long)by*8*5120; Bb = g_W1qb + (long)by*8*5120;
        cw = g_cw1; bias4v = g_bsum1p; cst = g_c1;
        oha = g_h2a[p^1]; ohb = g_h2b[p^1];
        nk = (t == 0) ? 4 : 8;
    }

    int hh[2][4][4], mm[2][4][4];
    #pragma unroll
    for (int i = 0; i < 2; i++)
        #pragma unroll
        for (int j = 0; j < 4; j++)
            #pragma unroll
            for (int q = 0; q < 4; q++){ hh[i][j][q] = 0; mm[i][j][q] = 0; }

    auto issue = [&](int kb, int st){
        uint32_t mbar = mb0 + st*8;
        mbar_expect(mbar, 30720);
        uint32_t dst = sb + st*QSTB;
        const int8_t* a0 = (kb < 4) ? Aa + (long)(bx*4 + kb)*10240
                                    : A2a + (long)(bx*4 + kb - 4)*10240;
        const int8_t* a1 = (kb < 4) ? Ab + (long)(bx*4 + kb)*10240
                                    : A2b + (long)(bx*4 + kb - 4)*10240;
        bulk_cp(dst + QAH, a0, 10240, mbar);
        bulk_cp(dst + QAL, a1, 10240, mbar);
        bulk_cp(dst + QBH, Ba + (long)kb*5120, 5120, mbar);
        bulk_cp(dst + QBL, Bb + (long)kb*5120, 5120, mbar);
    };

    if (tid == 0){ mbar_init(mb0, 1); mbar_init(mb0 + 8, 1); }
    __syncthreads();
    if (tid == 0) issue(0, 0);

    for (int kb = 0; kb < nk; kb++){
        const int st = kb & 1;
        MBAR_WAIT(mb0 + st*8, (kb >> 1) & 1);
        __syncthreads();          // all warps done with stage st^1 (chunk kb-1)
        if (kb + 1 < nk && tid == 0) issue(kb + 1, st ^ 1);
        uint32_t sbase = sb + st*QSTB;
        #pragma unroll
        for (int slab = 0; slab < 2; slab++){
            const int kbyte = slab*32 + (lane >> 4)*16;
            uint32_t aH[2][4], aL[2][4];
            #pragma unroll
            for (int mt = 0; mt < 2; mt++){
                uint32_t off = (wm*32 + mt*16 + (lane & 15))*80 + kbyte;
                ldsm4(aH[mt], sbase + QAH + off);
                ldsm4(aL[mt], sbase + QAL + off);
            }
            uint32_t bH[2][4], bL[2][4];
            #pragma unroll
            for (int nf2 = 0; nf2 < 2; nf2++){
                uint32_t boff = (wn*32 + nf2*16 + (lane >> 4)*8 + (lane & 7))*80
                              + slab*32 + ((lane >> 3) & 1)*16;
                ldsm4(bH[nf2], sbase + QBH + boff);
                ldsm4(bL[nf2], sbase + QBL + boff);
            }
            #pragma unroll
            for (int mt = 0; mt < 2; mt++)
                #pragma unroll
                for (int nf2 = 0; nf2 < 2; nf2++)
                    #pragma unroll
                    for (int sub = 0; sub < 2; sub++){
                        int nf = nf2*2 + sub;
                        imma8(hh[mt][nf], aH[mt], bH[nf2][2*sub], bH[nf2][2*sub+1]);
                        imma8(mm[mt][nf], aH[mt], bL[nf2][2*sub], bL[nf2][2*sub+1]);
                        imma8(mm[mt][nf], aL[mt], bH[nf2][2*sub], bH[nf2][2*sub+1]);
                    }
        }
    }

    // epilogue: fused LSTM cell (+ fused W_op projection for layer1)
    const int g = lane >> 2, t4 = lane & 3, odd = lane & 1;
    const int cbase = by*64 + wn*32;
    const int rbase = bx*128 + wm*32 + g;

    #pragma unroll
    for (int mt = 0; mt < 2; mt++){
        int row = rbase + mt*16 + odd*8;
        float s0 = 0.0f, s1 = 0.0f;
        #pragma unroll
        for (int nf = 0; nf < 4; nf++){
            int col0 = cbase + nf*8 + t4*2;
            float cs0 = cw[col0], cs1 = cw[col0 + 1];
            float c0 = cs0*fmaf(16384.0f, (float)hh[mt][nf][0], 128.0f*(float)mm[mt][nf][0]);
            float c1 = cs1*fmaf(16384.0f, (float)hh[mt][nf][1], 128.0f*(float)mm[mt][nf][1]);
            float c2 = cs0*fmaf(16384.0f, (float)hh[mt][nf][2], 128.0f*(float)mm[mt][nf][2]);
            float c3 = cs1*fmaf(16384.0f, (float)hh[mt][nf][3], 128.0f*(float)mm[mt][nf][3]);
            float sh0 = __shfl_xor_sync(0xffffffffu, c0, 1);
            float sh1 = __shfl_xor_sync(0xffffffffu, c1, 1);
            float sh2 = __shfl_xor_sync(0xffffffffu, c2, 1);
            float sh3 = __shfl_xor_sync(0xffffffffu, c3, 1);
            float gi, gf, gg, go;
            if (!odd){ gi = c0; gf = c1; gg = sh0; go = sh1; }
            else     { gi = sh2; gf = sh3; gg = c2; go = c3; }
            int cell = ((cbase + nf*8) >> 2) + (t4 >> 1);
            float4 bb = *(const float4*)&bias4v[cell*4];
            gi += bb.x; gf += bb.y; gg += bb.z; go += bb.w;
            if (m == 2){
                float4 gx = *(const float4*)&g_gx0[row*1024 + cell*4];
                gi += gx.x; gf += gx.y; gg += gx.z; go += gx.w;
            }
            float cold = cst[row*256 + cell];
            float cn = sigm(gf)*cold + sigm(gi)*tanhf(gg);
            float h  = sigm(go)*tanhf(cn);
            cst[row*256 + cell] = cn;
            long off = hoff(row, cell);
            qpack(h, oha[off], ohb[off]);
            if (m == 3){
                s0 = fmaf(h, Wop[cell], s0);
                s1 = fmaf(h, Wop[256 + cell], s1);
            }
        }
        if (m == 3){
            int rt = row*TT + t;
            atomicAdd(&out[rt*2],     s0);
            atomicAdd(&out[rt*2 + 1], s1);
        }
    }
}

// ---------------- endpoint + confidence ----------------
__global__ void epconf_k(const float* __restrict__ Wep, const float* __restrict__ bep,
                         const float* __restrict__ Wconf, const float* __restrict__ bconf,
                         float* __restrict__ out){
    int row = blockIdx.x*8 + (threadIdx.x >> 5);
    int lane = threadIdx.x & 31;
    const float* h = g_hidden + row*256;
    float s0 = 0.f, s1 = 0.f, s2 = 0.f;
    #pragma unroll
    for (int i = 0; i < 8; i++){
        float v = h[lane + i*32];
        s0 += v * Wep[lane + i*32];
        s1 += v * Wep[256 + lane + i*32];
        s2 += v * Wconf[lane + i*32];
    }
    #pragma unroll
    for (int o = 16; o; o >>= 1){
        s0 += __shfl_xor_sync(0xffffffffu, s0, o);
        s1 += __shfl_xor_sync(0xffffffffu, s1, o);
        s2 += __shfl_xor_sync(0xffffffffu, s2, o);
    }
    if (lane == 0){
        float e0 = s0 + bep[0], e1 = s1 + bep[1];
        g_ep[row*2] = e0; g_ep[row*2+1] = e1;
        out[OUT_EP + row*2] = e0; out[OUT_EP + row*2 + 1] = e1;
        out[OUT_CONF + row] = s2 + bconf[0];
    }
}

// ---------------- launch ----------------
extern "C" void kernel_launch(void* const* d_in, const int* in_sizes, int n_in,
                              void* d_out, int out_size){
    (void)in_sizes; (void)n_in; (void)out_size;
    const float* obs    = (const float*)d_in[0];
    const float* lanef  = (const float*)d_in[1];
    const float* ds     = (const float*)d_in[3];
    const float* W_hid  = (const float*)d_in[4];
    const float* b_hid  = (const float*)d_in[5];
    const float* W_ep   = (const float*)d_in[6];
    const float* b_ep   = (const float*)d_in[7];
    const float* W_conf = (const float*)d_in[8];
    const float* b_conf = (const float*)d_in[9];
    const float* W_ih0  = (const float*)d_in[10];
    const float* W_hh0  = (const float*)d_in[11];
    const float* b_ih0  = (const float*)d_in[12];
    const float* b_hh0  = (const float*)d_in[13];
    const float* W_ih1  = (const float*)d_in[14];
    const float* W_hh1  = (const float*)d_in[15];
    const float* b_ih1  = (const float*)d_in[16];
    const float* b_hh1  = (const float*)d_in[17];
    const float* W_op   = (const float*)d_in[18];
    const float* b_op   = (const float*)d_in[19];
    float* out = (float*)d_out;

    cudaFuncSetAttribute(gemm_k, cudaFuncAttributeMaxDynamicSharedMemorySize, 2*STB);
    cudaFuncSetAttribute(imma_k, cudaFuncAttributeMaxDynamicSharedMemorySize, 2*QSTB);

    prep_w<<<512, 256>>>(W_hid, W_ih0, b_ih0, b_hh0, b_ih1, b_hh1);
    prep_wq<<<256, 256>>>(W_hh0, W_ih1, W_hh1);
    prep_in<<<512, 256>>>(obs, lanef, ds, b_op, out);

    gemm_k<<<dim3(48, 2), 256, 2*STB>>>(0, b_hid);              // encoder
    epconf_k<<<768, 256>>>(W_ep, b_ep, W_conf, b_conf, out);    // endpoint + conf
    gemm_k<<<dim3(48, 8), 256, 2*STB>>>(1, nullptr);            // gx0 + layer0 t=0

    for (int t = 1; t < TT; t++){
        imma_k<<<dim3(48, 32), 256, 2*QSTB>>>(4, t & 1, t, W_op, out); // layer1(t-1)+layer0(t)
    }
    imma_k<<<dim3(48, 16), 256, 2*QSTB>>>(3, (TT-1) & 1, TT-1, W_op, out); // layer1 t=29
}

// round 13
// speedup vs baseline: 1.5700x; 1.3158x over previous
#include <cuda_runtime.h>
#include <cuda_bf16.h>
#include <stdint.h>
#include <math.h>

#define NR 6144
#define HD 256
#define G4 1024
#define TT 30
#define QS 16319.0f

// ---------------- static device scratch ----------------
__device__ __nv_bfloat16 g_comb_h[NR*HD], g_comb_l[NR*HD];
__device__ float         g_hidden[NR*HD];
__device__ __nv_bfloat16 g_hid_h[NR*HD], g_hid_l[NR*HD];
__device__ float         g_ep[NR*2];
__device__ float         g_gx0[NR*G4];
__device__ __nv_bfloat16 g_Whid_h[HD*HD], g_Whid_l[HD*HD];
__device__ __nv_bfloat16 g_Wih0_h[G4*HD], g_Wih0_l[G4*HD];
__device__ float g_Wih0ep[G4*2];
__device__ float g_bih0p[G4], g_bhh0p[G4], g_bsum1p[G4];
__device__ float g_c0[NR*HD], g_c1[NR*HD];
// int8 path — TILED layouts (80B-pitch smem images, contiguous per (tile,kchunk))
// h-state: [bx(96)][kc(4)][row(64)][80]
#define HTILE (96*4*64*80)
__device__ __align__(128) int8_t g_h0a[2][HTILE], g_h0b[2][HTILE];
__device__ __align__(128) int8_t g_h2a[2][HTILE], g_h2b[2][HTILE];
// weights: Whh0 [by(16)][kc(4)][row(64)][80]; W1 [by(16)][kc(8)][row(64)][80]
__device__ __align__(128) int8_t g_Whh0qa[16*4*64*80], g_Whh0qb[16*4*64*80];
__device__ __align__(128) int8_t g_W1qa[16*8*64*80],  g_W1qb[16*8*64*80];
__device__ float g_cwhh0[G4], g_cw1[G4];

#define OUT_CONF 368640
#define OUT_EP   374784

// ---------------- helpers ----------------
__device__ __forceinline__ void split2(float x, __nv_bfloat16& h, __nv_bfloat16& l){
    h = __float2bfloat16(x);
    l = __float2bfloat16(x - __bfloat162float(h));
}
__device__ __forceinline__ float sigm(float x){ return 1.0f/(1.0f+expf(-x)); }
__device__ __forceinline__ void qpack(float h, int8_t& a, int8_t& b){
    int hq = __float2int_rn(h * QS);
    int ha = (hq + 64) >> 7;
    a = (int8_t)ha; b = (int8_t)(hq - (ha << 7));
}
// tiled h-state offset: row in [0,6144) (64-row tiles), c = K-position in [0,256)
__device__ __forceinline__ long hoff(int row, int c){
    return ((long)((row >> 6)*4 + (c >> 6))*64 + (row & 63))*80 + (c & 63);
}
__device__ __forceinline__ uint32_t smem_u32(const void* p){
    uint32_t a;
    asm("{ .reg .u64 t; cvta.to.shared.u64 t, %1; cvt.u32.u64 %0, t; }" : "=r"(a) : "l"(p));
    return a;
}
__device__ __forceinline__ void cp16(void* sdst, const void* gsrc){
    unsigned sa = (unsigned)__cvta_generic_to_shared(sdst);
    asm volatile("cp.async.cg.shared.global [%0], [%1], 16;\n" :: "r"(sa), "l"(gsrc));
}
__device__ __forceinline__ void cp_commit(){ asm volatile("cp.async.commit_group;\n"); }
__device__ __forceinline__ void cp_wait0(){ asm volatile("cp.async.wait_group 0;\n"); }
__device__ __forceinline__ void bulk_cp(uint32_t dst, const void* src, uint32_t bytes, uint32_t mbar){
    asm volatile("cp.async.bulk.shared::cluster.global.mbarrier::complete_tx::bytes [%0], [%1], %2, [%3];"
        :: "r"(dst), "l"(src), "r"(bytes), "r"(mbar) : "memory");
}
__device__ __forceinline__ void mbar_init(uint32_t a, uint32_t cnt){
    asm volatile("mbarrier.init.shared.b64 [%0], %1;" :: "r"(a), "r"(cnt) : "memory");
}
__device__ __forceinline__ void mbar_expect(uint32_t a, uint32_t bytes){
    asm volatile("mbarrier.arrive.expect_tx.shared.b64 _, [%0], %1;" :: "r"(a), "r"(bytes) : "memory");
}
#define MBAR_WAIT(mb, ph) do { \
    uint32_t _mb = (mb), _p = (ph), _done; \
    asm volatile("{\n\t.reg .pred p;\n\t" \
        "mbarrier.try_wait.parity.acquire.cta.shared::cta.b64 p, [%1], %2;\n\t" \
        "selp.b32 %0, 1, 0, p;\n\t}" : "=r"(_done) : "r"(_mb), "r"(_p) : "memory"); \
    if (!_done) { \
        asm volatile("{\n\t.reg .pred P1;\n\t" \
            "WL_%=:\n\t" \
            "mbarrier.try_wait.parity.acquire.cta.shared::cta.b64 P1, [%0], %1, 0x989680;\n\t" \
            "@P1 bra.uni WD_%=;\n\t" \
            "bra.uni WL_%=;\n\t" \
            "WD_%=:\n\t}" :: "r"(_mb), "r"(_p) : "memory"); \
    } \
} while(0)
__device__ __forceinline__ void ldsm4(uint32_t* r, uint32_t a){
    asm volatile("ldmatrix.sync.aligned.m8n8.x4.shared.b16 {%0,%1,%2,%3},[%4];\n"
        : "=r"(r[0]), "=r"(r[1]), "=r"(r[2]), "=r"(r[3]) : "r"(a));
}
__device__ __forceinline__ void mma_bf16(float* c, const uint32_t* a, uint32_t b0, uint32_t b1){
    asm volatile("mma.sync.aligned.m16n8k16.row.col.f32.bf16.bf16.f32 "
        "{%0,%1,%2,%3},{%4,%5,%6,%7},{%8,%9},{%0,%1,%2,%3};\n"
        : "+f"(c[0]), "+f"(c[1]), "+f"(c[2]), "+f"(c[3])
        : "r"(a[0]), "r"(a[1]), "r"(a[2]), "r"(a[3]), "r"(b0), "r"(b1));
}
__device__ __forceinline__ void imma8(int* c, const uint32_t* a, uint32_t b0, uint32_t b1){
    asm volatile("mma.sync.aligned.m16n8k32.row.col.s32.s8.s8.s32 "
        "{%0,%1,%2,%3},{%4,%5,%6,%7},{%8,%9},{%0,%1,%2,%3};\n"
        : "+r"(c[0]), "+r"(c[1]), "+r"(c[2]), "+r"(c[3])
        : "r"(a[0]), "r"(a[1]), "r"(a[2]), "r"(a[3]), "r"(b0), "r"(b1));
}

// ---------------- prep ----------------
__global__ void prep_w(const float* __restrict__ Whid, const float* __restrict__ Wih0,
                       const float* __restrict__ bih0, const float* __restrict__ bhh0,
                       const float* __restrict__ bih1, const float* __restrict__ bhh1){
    const int T0 = 65536, T1 = T0 + 262144, T2 = T1 + 1024;
    for (int i = blockIdx.x*blockDim.x + threadIdx.x; i < T2; i += gridDim.x*blockDim.x){
        if (i < T0){
            split2(Whid[i], g_Whid_h[i], g_Whid_l[i]);
        } else if (i < T1){
            int j = i - T0; int p = j >> 8, k = j & 255;
            int sr = (p & 3)*256 + (p >> 2);
            split2(Wih0[sr*258 + k], g_Wih0_h[j], g_Wih0_l[j]);
        } else {
            int p = i - T1;
            int sr = (p & 3)*256 + (p >> 2);
            g_bih0p[p]  = bih0[sr];
            g_bhh0p[p]  = bhh0[sr];
            g_bsum1p[p] = bih1[sr] + bhh1[sr];
            g_Wih0ep[p*2]   = Wih0[sr*258 + 256];
            g_Wih0ep[p*2+1] = Wih0[sr*258 + 257];
        }
    }
}

__global__ void prep_wq(const float* __restrict__ Whh0, const float* __restrict__ Wih1,
                        const float* __restrict__ Whh1){
    int task = blockIdx.x*8 + (threadIdx.x >> 5);
    int lane = threadIdx.x & 31;
    if (task >= 2048) return;
    bool isW1 = task >= 1024;
    int p  = isW1 ? task - 1024 : task;
    int sr = (p & 3)*256 + (p >> 2);
    int K  = isW1 ? 512 : 256;
    float mx = 0.0f;
    for (int k = lane; k < K; k += 32){
        float w = isW1 ? (k < 256 ? Wih1[sr*256 + k] : Whh1[sr*256 + (k - 256)])
                       : Whh0[sr*256 + k];
        mx = fmaxf(mx, fabsf(w));
    }
    #pragma unroll
    for (int o = 16; o; o >>= 1) mx = fmaxf(mx, __shfl_xor_sync(0xffffffffu, mx, o));
    float scale = QS / fmaxf(mx, 1e-20f);
    int nkc = isW1 ? 8 : 4;
    for (int k = lane; k < K; k += 32){
        float w = isW1 ? (k < 256 ? Wih1[sr*256 + k] : Whh1[sr*256 + (k - 256)])
                       : Whh0[sr*256 + k];
        int q = __float2int_rn(w * scale);
        int a = (q + 64) >> 7;
        int b = q - (a << 7);
        long off = ((long)((p >> 6)*nkc + (k >> 6))*64 + (p & 63))*80 + (k & 63);
        if (isW1){ g_W1qa[off] = (int8_t)a; g_W1qb[off] = (int8_t)b; }
        else     { g_Whh0qa[off] = (int8_t)a; g_Whh0qb[off] = (int8_t)b; }
    }
    if (lane == 0){
        float c = mx / (QS * QS);
        if (isW1) g_cw1[p] = c; else g_cwhh0[p] = c;
    }
}

__global__ void prep_in(const float* __restrict__ obs, const float* __restrict__ lanef,
                        const float* __restrict__ ds, const float* __restrict__ bop,
                        float* __restrict__ out){
    for (int idx = blockIdx.x*blockDim.x + threadIdx.x; idx < NR*HD; idx += gridDim.x*blockDim.x){
        int row = idx >> 8, col = idx & 255;
        int b = row / 6, kk = row - b*6;
        float v;
        if (col < 128)      v = obs[b*128 + col];
        else if (col < 192) v = lanef[b*64 + (col - 128)];
        else                v = ds[kk*64 + (col - 192)];
        split2(v, g_comb_h[idx], g_comb_l[idx]);
        g_c1[idx] = 0.0f;
        if (idx < OUT_CONF) out[idx] = bop[idx & 1];   // seed final outputs with bias
    }
}

// ---------------- bf16 split GEMM: 0=encoder, 1=gx0 (+fused layer0 t=0) ----------------
#define AHI 0
#define ALO 10240
#define BHI 20480
#define BLO 30720
#define STB 40960

__global__ void __launch_bounds__(256, 2)
gemm_k(int mode, const float* __restrict__ bvec)
{
    extern __shared__ __align__(128) char smem[];
    const int tid = threadIdx.x, lane = tid & 31, w = tid >> 5;
    const int wm = w >> 1, wn = w & 1;
    const int bx = blockIdx.x, by = blockIdx.y;

    const __nv_bfloat16 *Ah, *Al, *Bh, *Bl;
    if (mode == 0){ Ah=g_comb_h; Al=g_comb_l; Bh=g_Whid_h; Bl=g_Whid_l; }
    else          { Ah=g_hid_h;  Al=g_hid_l;  Bh=g_Wih0_h; Bl=g_Wih0_l; }

    float acc[2][8][4];
    #pragma unroll
    for (int i = 0; i < 2; i++)
        #pragma unroll
        for (int j = 0; j < 8; j++)
            #pragma unroll
            for (int q = 0; q < 4; q++) acc[i][j][q] = 0.0f;

    const int lrow = tid >> 1, lcg = (tid & 1) * 16;

    auto prefetch = [&](int kb, int st){
        int k0 = kb * 32;
        char* sb = smem + st * STB;
        const __nv_bfloat16* as  = Ah + (bx*128 + lrow)*256 + k0 + lcg;
        const __nv_bfloat16* as2 = Al + (bx*128 + lrow)*256 + k0 + lcg;
        int so = (lrow*40 + lcg)*2;
        cp16(sb + AHI + so, as);   cp16(sb + AHI + so + 16, as + 8);
        cp16(sb + ALO + so, as2);  cp16(sb + ALO + so + 16, as2 + 8);
        const __nv_bfloat16* bs  = Bh + (long)(by*128 + lrow)*256 + k0 + lcg;
        const __nv_bfloat16* bs2 = Bl + (long)(by*128 + lrow)*256 + k0 + lcg;
        cp16(sb + BHI + so, bs);   cp16(sb + BHI + so + 16, bs + 8);
        cp16(sb + BLO + so, bs2);  cp16(sb + BLO + so + 16, bs2 + 8);
        cp_commit();
    };

    prefetch(0, 0);
    for (int kb = 0; kb < 8; kb++){
        const int st = kb & 1;
        cp_wait0();
        __syncthreads();
        if (kb + 1 < 8) prefetch(kb + 1, st ^ 1);
        uint32_t sbase = (uint32_t)__cvta_generic_to_shared(smem) + st*STB;
        #pragma unroll
        for (int ks = 0; ks < 2; ks++){
            uint32_t ah[2][4], al[2][4];
            const int acol = ks*16 + (lane >> 4)*8;
            #pragma unroll
            for (int mt = 0; mt < 2; mt++){
                uint32_t off = ((wm*32 + mt*16 + (lane & 15))*40 + acol)*2;
                ldsm4(ah[mt], sbase + AHI + off);
                ldsm4(al[mt], sbase + ALO + off);
            }
            #pragma unroll
            for (int np = 0; np < 4; np++){
                uint32_t bh[4], bl[4];
                const int nr = wn*64 + np*16 + (lane >> 4)*8 + (lane & 7);
                const int nc = ks*16 + ((lane >> 3) & 1)*8;
                uint32_t boff = (nr*40 + nc)*2;
                ldsm4(bh, sbase + BHI + boff);
                ldsm4(bl, sbase + BLO + boff);
                #pragma unroll
                for (int mt = 0; mt < 2; mt++)
                    #pragma unroll
                    for (int sub = 0; sub < 2; sub++){
                        float* c = acc[mt][np*2 + sub];
                        mma_bf16(c, ah[mt], bh[2*sub], bh[2*sub+1]);
                        mma_bf16(c, ah[mt], bl[2*sub], bl[2*sub+1]);
                        mma_bf16(c, al[mt], bh[2*sub], bh[2*sub+1]);
                    }
            }
        }
    }

    const int g = lane >> 2, t4 = lane & 3, odd = lane & 1;
    const int cbase = by*128 + wn*64;
    const int rbase = bx*128 + wm*32 + g;

    if (mode == 0){
        #pragma unroll
        for (int mt = 0; mt < 2; mt++)
            #pragma unroll
            for (int half = 0; half < 2; half++){
                int row = rbase + mt*16 + half*8;
                #pragma unroll
                for (int nt = 0; nt < 8; nt++)
                    #pragma unroll
                    for (int q = 0; q < 2; q++){
                        int col = cbase + nt*8 + t4*2 + q;
                        float v = acc[mt][nt][half*2 + q] + bvec[col];
                        v = (v > 0.0f) ? v : 0.1f*v;
                        g_hidden[row*256 + col] = v;
                        split2(v, g_hid_h[row*256 + col], g_hid_l[row*256 + col]);
                    }
            }
    } else {
        // gx0 write + fused layer0 t=0 (h=0 -> gates = gx0 + b_hh0, c_old = 0)
        #pragma unroll
        for (int mt = 0; mt < 2; mt++){
            int r0 = rbase + mt*16;
            float e0a = g_ep[r0*2],     e1a = g_ep[r0*2+1];
            float e0b = g_ep[(r0+8)*2], e1b = g_ep[(r0+8)*2+1];
            #pragma unroll
            for (int nt = 0; nt < 8; nt++){
                int col0 = cbase + nt*8 + t4*2, col1 = col0 + 1;
                float w00 = g_Wih0ep[col0*2], w01 = g_Wih0ep[col0*2+1];
                float w10 = g_Wih0ep[col1*2], w11 = g_Wih0ep[col1*2+1];
                float bi0 = g_bih0p[col0], bi1 = g_bih0p[col1];
                float v0 = acc[mt][nt][0] + bi0 + e0a*w00 + e1a*w01;
                float v1 = acc[mt][nt][1] + bi1 + e0a*w10 + e1a*w11;
                float v2 = acc[mt][nt][2] + bi0 + e0b*w00 + e1b*w01;
                float v3 = acc[mt][nt][3] + bi1 + e0b*w10 + e1b*w11;
                g_gx0[r0*1024 + col0]     = v0;
                g_gx0[r0*1024 + col1]     = v1;
                g_gx0[(r0+8)*1024 + col0] = v2;
                g_gx0[(r0+8)*1024 + col1] = v3;
                float bh0 = g_bhh0p[col0], bh1 = g_bhh0p[col1];
                float c0 = v0 + bh0, c1 = v1 + bh1, c2 = v2 + bh0, c3 = v3 + bh1;
                float s0 = __shfl_xor_sync(0xffffffffu, c0, 1);
                float s1 = __shfl_xor_sync(0xffffffffu, c1, 1);
                float s2 = __shfl_xor_sync(0xffffffffu, c2, 1);
                float s3 = __shfl_xor_sync(0xffffffffu, c3, 1);
                float gi, gg, go;
                if (!odd){ gi = c0; gg = s0; go = s1; }
                else     { gi = s2; gg = c2; go = c3; }
                int cell = ((cbase + nt*8) >> 2) + (t4 >> 1);
                int row = r0 + odd*8;
                float cn = sigm(gi)*tanhf(gg);
                float h  = sigm(go)*tanhf(cn);
                g_c0[row*256 + cell] = cn;
                long off = hoff(row, cell);
                qpack(h, g_h0a[1][off], g_h0b[1][off]);
            }
        }
    }
}

// ---------------- int8 IMMA GEMM + fused LSTM (M64xN64 tile, 3 CTAs/SM) ----------------
#define QAH 0
#define QAL 5120
#define QBH 10240
#define QBL 15360
#define QSTB 20480

__global__ void __launch_bounds__(256, 3)
imma_k(int mode, int pp, int tstep, const float* __restrict__ Wop, float* __restrict__ out)
{
    extern __shared__ __align__(128) char smem[];
    __shared__ __align__(8) uint64_t mbars[2];
    const uint32_t sb = smem_u32(smem);
    const uint32_t mb0 = smem_u32(&mbars[0]);
    const int tid = threadIdx.x, lane = tid & 31, w = tid >> 5;
    const int wm = w >> 1, wn = w & 1;
    const int bx = blockIdx.x;

    int m = mode, by = blockIdx.y, p = pp, t = tstep;
    if (mode == 4){
        if (by < 16){ m = 3; p = pp ^ 1; t = tstep - 1; }
        else        { m = 2; by -= 16; }
    }

    const int8_t *Aa, *Ab, *A2a = nullptr, *A2b = nullptr, *Ba, *Bb;
    const float *cw, *bias4v; float* cst; int8_t *oha, *ohb;
    int nk;
    if (m == 2){
        Aa = g_h0a[p]; Ab = g_h0b[p];
        Ba = g_Whh0qa + (long)by*4*5120; Bb = g_Whh0qb + (long)by*4*5120;
        cw = g_cwhh0; bias4v = g_bhh0p; cst = g_c0;
        oha = g_h0a[p^1]; ohb = g_h0b[p^1];
        nk = 4;
    } else {
        Aa = g_h0a[p^1]; Ab = g_h0b[p^1]; A2a = g_h2a[p]; A2b = g_h2b[p];
        Ba = g_W1qa + (long)by*8*5120; Bb = g_W1qb + (long)by*8*5120;
        cw = g_cw1; bias4v = g_bsum1p; cst = g_c1;
        oha = g_h2a[p^1]; ohb = g_h2b[p^1];
        nk = (t == 0) ? 4 : 8;
    }

    int hh[4][4], mm[4][4];
    #pragma unroll
    for (int j = 0; j < 4; j++)
        #pragma unroll
        for (int q = 0; q < 4; q++){ hh[j][q] = 0; mm[j][q] = 0; }

    auto issue = [&](int kb, int st){
        uint32_t mbar = mb0 + st*8;
        mbar_expect(mbar, 20480);
        uint32_t dst = sb + st*QSTB;
        const int8_t* a0 = (kb < 4) ? Aa + (long)(bx*4 + kb)*5120
                                    : A2a + (long)(bx*4 + kb - 4)*5120;
        const int8_t* a1 = (kb < 4) ? Ab + (long)(bx*4 + kb)*5120
                                    : A2b + (long)(bx*4 + kb - 4)*5120;
        bulk_cp(dst + QAH, a0, 5120, mbar);
        bulk_cp(dst + QAL, a1, 5120, mbar);
        bulk_cp(dst + QBH, Ba + (long)kb*5120, 5120, mbar);
        bulk_cp(dst + QBL, Bb + (long)kb*5120, 5120, mbar);
    };

    if (tid == 0){ mbar_init(mb0, 1); mbar_init(mb0 + 8, 1); }
    __syncthreads();
    if (tid == 0) issue(0, 0);

    for (int kb = 0; kb < nk; kb++){
        const int st = kb & 1;
        MBAR_WAIT(mb0 + st*8, (kb >> 1) & 1);
        __syncthreads();          // all warps done with stage st^1 (chunk kb-1)
        if (kb + 1 < nk && tid == 0) issue(kb + 1, st ^ 1);
        uint32_t sbase = sb + st*QSTB;
        #pragma unroll
        for (int slab = 0; slab < 2; slab++){
            const int kbyte = slab*32 + (lane >> 4)*16;
            uint32_t aH[4], aL[4];
            {
                uint32_t off = (wm*16 + (lane & 15))*80 + kbyte;
                ldsm4(aH, sbase + QAH + off);
                ldsm4(aL, sbase + QAL + off);
            }
            uint32_t bH[2][4], bL[2][4];
            #pragma unroll
            for (int nf2 = 0; nf2 < 2; nf2++){
                uint32_t boff = (wn*32 + nf2*16 + (lane >> 4)*8 + (lane & 7))*80
                              + slab*32 + ((lane >> 3) & 1)*16;
                ldsm4(bH[nf2], sbase + QBH + boff);
                ldsm4(bL[nf2], sbase + QBL + boff);
            }
            #pragma unroll
            for (int nf2 = 0; nf2 < 2; nf2++)
                #pragma unroll
                for (int sub = 0; sub < 2; sub++){
                    int nf = nf2*2 + sub;
                    imma8(hh[nf], aH, bH[nf2][2*sub], bH[nf2][2*sub+1]);
                    imma8(mm[nf], aH, bL[nf2][2*sub], bL[nf2][2*sub+1]);
                    imma8(mm[nf], aL, bH[nf2][2*sub], bH[nf2][2*sub+1]);
                }
        }
    }

    // epilogue: fused LSTM cell (+ fused W_op projection for layer1)
    const int g = lane >> 2, t4 = lane & 3, odd = lane & 1;
    const int cbase = by*64 + wn*32;
    const int row = bx*64 + wm*16 + g + odd*8;

    float s0 = 0.0f, s1 = 0.0f;
    #pragma unroll
    for (int nf = 0; nf < 4; nf++){
        int col0 = cbase + nf*8 + t4*2;
        float cs0 = cw[col0], cs1 = cw[col0 + 1];
        float c0 = cs0*fmaf(16384.0f, (float)hh[nf][0], 128.0f*(float)mm[nf][0]);
        float c1 = cs1*fmaf(16384.0f, (float)hh[nf][1], 128.0f*(float)mm[nf][1]);
        float c2 = cs0*fmaf(16384.0f, (float)hh[nf][2], 128.0f*(float)mm[nf][2]);
        float c3 = cs1*fmaf(16384.0f, (float)hh[nf][3], 128.0f*(float)mm[nf][3]);
        float sh0 = __shfl_xor_sync(0xffffffffu, c0, 1);
        float sh1 = __shfl_xor_sync(0xffffffffu, c1, 1);
        float sh2 = __shfl_xor_sync(0xffffffffu, c2, 1);
        float sh3 = __shfl_xor_sync(0xffffffffu, c3, 1);
        float gi, gf, gg, go;
        if (!odd){ gi = c0; gf = c1; gg = sh0; go = sh1; }
        else     { gi = sh2; gf = sh3; gg = c2; go = c3; }
        int cell = ((cbase + nf*8) >> 2) + (t4 >> 1);
        float4 bb = *(const float4*)&bias4v[cell*4];
        gi += bb.x; gf += bb.y; gg += bb.z; go += bb.w;
        if (m == 2){
            float4 gx = *(const float4*)&g_gx0[row*1024 + cell*4];
            gi += gx.x; gf += gx.y; gg += gx.z; go += gx.w;
        }
        float cold = cst[row*256 + cell];
        float cn = sigm(gf)*cold + sigm(gi)*tanhf(gg);
        float h  = sigm(go)*tanhf(cn);
        cst[row*256 + cell] = cn;
        long off = hoff(row, cell);
        qpack(h, oha[off], ohb[off]);
        if (m == 3){
            s0 = fmaf(h, Wop[cell], s0);
            s1 = fmaf(h, Wop[256 + cell], s1);
        }
    }
    if (m == 3){
        int rt = row*TT + t;
        atomicAdd(&out[rt*2],     s0);
        atomicAdd(&out[rt*2 + 1], s1);
    }
}

// ---------------- endpoint + confidence ----------------
__global__ void epconf_k(const float* __restrict__ Wep, const float* __restrict__ bep,
                         const float* __restrict__ Wconf, const float* __restrict__ bconf,
                         float* __restrict__ out){
    int row = blockIdx.x*8 + (threadIdx.x >> 5);
    int lane = threadIdx.x & 31;
    const float* h = g_hidden + row*256;
    float s0 = 0.f, s1 = 0.f, s2 = 0.f;
    #pragma unroll
    for (int i = 0; i < 8; i++){
        float v = h[lane + i*32];
        s0 += v * Wep[lane + i*32];
        s1 += v * Wep[256 + lane + i*32];
        s2 += v * Wconf[lane + i*32];
    }
    #pragma unroll
    for (int o = 16; o; o >>= 1){
        s0 += __shfl_xor_sync(0xffffffffu, s0, o);
        s1 += __shfl_xor_sync(0xffffffffu, s1, o);
        s2 += __shfl_xor_sync(0xffffffffu, s2, o);
    }
    if (lane == 0){
        float e0 = s0 + bep[0], e1 = s1 + bep[1];
        g_ep[row*2] = e0; g_ep[row*2+1] = e1;
        out[OUT_EP + row*2] = e0; out[OUT_EP + row*2 + 1] = e1;
        out[OUT_CONF + row] = s2 + bconf[0];
    }
}

// ---------------- launch ----------------
extern "C" void kernel_launch(void* const* d_in, const int* in_sizes, int n_in,
                              void* d_out, int out_size){
    (void)in_sizes; (void)n_in; (void)out_size;
    const float* obs    = (const float*)d_in[0];
    const float* lanef  = (const float*)d_in[1];
    const float* ds     = (const float*)d_in[3];
    const float* W_hid  = (const float*)d_in[4];
    const float* b_hid  = (const float*)d_in[5];
    const float* W_ep   = (const float*)d_in[6];
    const float* b_ep   = (const float*)d_in[7];
    const float* W_conf = (const float*)d_in[8];
    const float* b_conf = (const float*)d_in[9];
    const float* W_ih0  = (const float*)d_in[10];
    const float* W_hh0  = (const float*)d_in[11];
    const float* b_ih0  = (const float*)d_in[12];
    const float* b_hh0  = (const float*)d_in[13];
    const float* W_ih1  = (const float*)d_in[14];
    const float* W_hh1  = (const float*)d_in[15];
    const float* b_ih1  = (const float*)d_in[16];
    const float* b_hh1  = (const float*)d_in[17];
    const float* W_op   = (const float*)d_in[18];
    const float* b_op   = (const float*)d_in[19];
    float* out = (float*)d_out;

    cudaFuncSetAttribute(gemm_k, cudaFuncAttributeMaxDynamicSharedMemorySize, 2*STB);
    cudaFuncSetAttribute(imma_k, cudaFuncAttributeMaxDynamicSharedMemorySize, 2*QSTB);

    prep_w<<<512, 256>>>(W_hid, W_ih0, b_ih0, b_hh0, b_ih1, b_hh1);
    prep_wq<<<256, 256>>>(W_hh0, W_ih1, W_hh1);
    prep_in<<<512, 256>>>(obs, lanef, ds, b_op, out);

    gemm_k<<<dim3(48, 2), 256, 2*STB>>>(0, b_hid);              // encoder
    epconf_k<<<768, 256>>>(W_ep, b_ep, W_conf, b_conf, out);    // endpoint + conf
    gemm_k<<<dim3(48, 8), 256, 2*STB>>>(1, nullptr);            // gx0 + layer0 t=0

    for (int t = 1; t < TT; t++){
        imma_k<<<dim3(96, 32), 256, 2*QSTB>>>(4, t & 1, t, W_op, out); // layer1(t-1)+layer0(t)
    }
    imma_k<<<dim3(96, 16), 256, 2*QSTB>>>(3, (TT-1) & 1, TT-1, W_op, out); // layer1 t=29
}